// round 2
// baseline (speedup 1.0000x reference)
#include <cuda_runtime.h>
#include <cuda_bf16.h>
#include <math_constants.h>

// Problem constants
#define BB 128
#define TT 128
#define CC 256
#define HH 4
#define LL 6
#define VV 10000
#define HS 64
#define DFF 1024
#define MROWS (BB*TT)   // 16384

// ---------------------------------------------------------------------------
// Scratch (device globals; no allocation allowed)
// ---------------------------------------------------------------------------
__device__ float g_x  [MROWS*CC];
__device__ float g_h  [MROWS*CC];
__device__ float g_q  [MROWS*CC];
__device__ float g_k  [MROWS*CC];
__device__ float g_v  [MROWS*CC];
__device__ float g_att[MROWS*CC];
__device__ float g_ff [MROWS*DFF];

// ---------------------------------------------------------------------------
// Embedding: x[b,t,:] = tok_emb[idx[b,t]] + pos_emb[t]
// ---------------------------------------------------------------------------
__global__ void embed_kernel(const int* __restrict__ idx,
                             const float* __restrict__ tok,
                             const float* __restrict__ pos,
                             float* __restrict__ x)
{
    int row = blockIdx.x;          // 0..16383
    int tid = threadIdx.x;         // 0..255
    int token = idx[row];
    x[(size_t)row*CC + tid] = tok[(size_t)token*CC + tid] + pos[(row & (TT-1))*CC + tid];
}

// ---------------------------------------------------------------------------
// LayerNorm (block per row, C=256 threads). out = (x-m)/sqrt(v+eps)*g + b
// ---------------------------------------------------------------------------
__global__ void ln_kernel(const float* __restrict__ x,
                          const float* __restrict__ g,
                          const float* __restrict__ b,
                          float* __restrict__ out)
{
    int row = blockIdx.x;
    int tid = threadIdx.x;
    __shared__ float red[8];

    float v = x[(size_t)row*CC + tid];

    // mean
    float s = v;
    #pragma unroll
    for (int o = 16; o; o >>= 1) s += __shfl_down_sync(0xffffffffu, s, o);
    if ((tid & 31) == 0) red[tid >> 5] = s;
    __syncthreads();
    if (tid < 8) {
        s = red[tid];
        #pragma unroll
        for (int o = 4; o; o >>= 1) s += __shfl_down_sync(0xffu, s, o);
        if (tid == 0) red[0] = s;
    }
    __syncthreads();
    float mean = red[0] * (1.f/CC);
    __syncthreads();

    // variance
    float d = v - mean;
    float s2 = d * d;
    #pragma unroll
    for (int o = 16; o; o >>= 1) s2 += __shfl_down_sync(0xffffffffu, s2, o);
    if ((tid & 31) == 0) red[tid >> 5] = s2;
    __syncthreads();
    if (tid < 8) {
        s2 = red[tid];
        #pragma unroll
        for (int o = 4; o; o >>= 1) s2 += __shfl_down_sync(0xffu, s2, o);
        if (tid == 0) red[0] = s2;
    }
    __syncthreads();
    float var = red[0] * (1.f/CC);

    out[(size_t)row*CC + tid] = d * rsqrtf(var + 1e-5f) * g[tid] + b[tid];
}

// ---------------------------------------------------------------------------
// GEMM: C[M,N] = A[M,K] @ B[K,N] (+bias[N]) (+resid[M,N]) (optional relu)
// Tiling: 128x128x16, 256 threads, 8x8 per thread.
// Requirements: M % 128 == 0, K % 16 == 0, N % 4 == 0 (all satisfied here).
// ---------------------------------------------------------------------------
__global__ __launch_bounds__(256) void gemm_kernel(
    const float* __restrict__ A, const float* __restrict__ B,
    const float* __restrict__ bias, const float* __restrict__ resid,
    float* __restrict__ C, int M, int N, int K, int relu)
{
    __shared__ float As[16][128];
    __shared__ float Bs[16][128];

    int tid  = threadIdx.x;
    int tx   = tid & 15;      // 0..15 -> col group
    int ty   = tid >> 4;      // 0..15 -> row group
    int row0 = blockIdx.y * 128;
    int col0 = blockIdx.x * 128;

    float acc[8][8];
    #pragma unroll
    for (int i = 0; i < 8; i++)
        #pragma unroll
        for (int j = 0; j < 8; j++) acc[i][j] = 0.f;

    for (int kt = 0; kt < K; kt += 16) {
        // --- load A tile (128x16) and B tile (16x128) ---
        #pragma unroll
        for (int it = 0; it < 2; it++) {
            int e = tid + it * 256;            // 0..511 float4 slots
            // A: 128 rows x 4 float4-cols
            int ar = e >> 2;
            int ac = (e & 3) * 4;
            float4 a = *(const float4*)&A[(size_t)(row0 + ar) * K + kt + ac];
            As[ac+0][ar] = a.x; As[ac+1][ar] = a.y;
            As[ac+2][ar] = a.z; As[ac+3][ar] = a.w;
            // B: 16 rows x 32 float4-cols
            int br = e >> 5;
            int bc = (e & 31) * 4;
            float4 bv;
            if (col0 + bc < N)
                bv = *(const float4*)&B[(size_t)(kt + br) * N + col0 + bc];
            else
                bv = make_float4(0.f, 0.f, 0.f, 0.f);
            *(float4*)&Bs[br][bc] = bv;
        }
        __syncthreads();

        #pragma unroll
        for (int k = 0; k < 16; k++) {
            float4 a0 = *(float4*)&As[k][ty*8];
            float4 a1 = *(float4*)&As[k][ty*8 + 4];
            float4 b0 = *(float4*)&Bs[k][tx*8];
            float4 b1 = *(float4*)&Bs[k][tx*8 + 4];
            float ra[8] = {a0.x,a0.y,a0.z,a0.w,a1.x,a1.y,a1.z,a1.w};
            float rb[8] = {b0.x,b0.y,b0.z,b0.w,b1.x,b1.y,b1.z,b1.w};
            #pragma unroll
            for (int i = 0; i < 8; i++)
                #pragma unroll
                for (int j = 0; j < 8; j++)
                    acc[i][j] += ra[i] * rb[j];
        }
        __syncthreads();
    }

    // --- epilogue ---
    #pragma unroll
    for (int i = 0; i < 8; i++) {
        int r = row0 + ty*8 + i;
        #pragma unroll
        for (int j = 0; j < 8; j++) {
            int c = col0 + tx*8 + j;
            if (c < N) {
                float v = acc[i][j];
                if (bias)  v += bias[c];
                if (resid) v += resid[(size_t)r * N + c];
                if (relu)  v = fmaxf(v, 0.f);
                C[(size_t)r * N + c] = v;
            }
        }
    }
}

// ---------------------------------------------------------------------------
// Attention: block per (b,h), thread = query row. Online softmax over keys.
// Q,K,V layout: [B,T,H,HS]; output att: [B,T,H*HS] == same layout.
// scale = C^-0.5 = 1/16 (matches reference's n_embd scaling).
// ---------------------------------------------------------------------------
__global__ __launch_bounds__(128) void attn_kernel(
    const float* __restrict__ Q, const float* __restrict__ K,
    const float* __restrict__ V, float* __restrict__ O)
{
    __shared__ float ks[64][64];
    __shared__ float vs[64][64];

    int bh = blockIdx.x;
    int b  = bh >> 2;          // H = 4
    int h  = bh & 3;
    int t  = threadIdx.x;      // query row 0..127
    const float scale = 0.0625f;

    const float* qp = Q + (((size_t)b*TT + t)*HH + h)*HS;
    float q[HS];
    #pragma unroll
    for (int d = 0; d < HS; d++) q[d] = qp[d] * scale;

    float m = -CUDART_INF_F;
    float s = 0.f;
    float acc[HS];
    #pragma unroll
    for (int d = 0; d < HS; d++) acc[d] = 0.f;

    for (int kc = 0; kc < TT; kc += 64) {
        __syncthreads();
        // cooperative chunk load: 64 rows x 16 float4 per array
        for (int i = t; i < 64*16; i += 128) {
            int r = i >> 4;
            int c = (i & 15) * 4;
            size_t goff = (((size_t)b*TT + kc + r)*HH + h)*HS + c;
            *(float4*)&ks[r][c] = *(const float4*)&K[goff];
            *(float4*)&vs[r][c] = *(const float4*)&V[goff];
        }
        __syncthreads();

        int jmax = t - kc + 1;
        if (jmax > 64) jmax = 64;
        for (int j = 0; j < jmax; j++) {
            float sc = 0.f;
            #pragma unroll
            for (int d = 0; d < HS; d++) sc += q[d] * ks[j][d];
            float nm = fmaxf(m, sc);
            float f  = __expf(m  - nm);
            float e  = __expf(sc - nm);
            s = s * f + e;
            #pragma unroll
            for (int d = 0; d < HS; d++) acc[d] = acc[d] * f + e * vs[j][d];
            m = nm;
        }
    }

    float inv = 1.f / s;
    float* op = O + (((size_t)b*TT + t)*HH + h)*HS;
    #pragma unroll
    for (int d = 0; d < HS; d++) op[d] = acc[d] * inv;
}

// ---------------------------------------------------------------------------
// Launch
// ---------------------------------------------------------------------------
static inline void launch_gemm(const float* A, const float* B, const float* bias,
                               const float* resid, float* C,
                               int M, int N, int K, int relu)
{
    dim3 grid((N + 127) / 128, M / 128);
    gemm_kernel<<<grid, 256>>>(A, B, bias, resid, C, M, N, K, relu);
}

extern "C" void kernel_launch(void* const* d_in, const int* in_sizes, int n_in,
                              void* d_out, int out_size)
{
    const int*   idx     = (const int*)  d_in[0];
    const float* tok_emb = (const float*)d_in[1];
    const float* pos_emb = (const float*)d_in[2];
    const float* ln1_g   = (const float*)d_in[3];
    const float* ln1_b   = (const float*)d_in[4];
    const float* wq      = (const float*)d_in[5];
    const float* wk      = (const float*)d_in[6];
    const float* wv      = (const float*)d_in[7];
    const float* proj_w  = (const float*)d_in[8];
    const float* proj_b  = (const float*)d_in[9];
    const float* ln2_g   = (const float*)d_in[10];
    const float* ln2_b   = (const float*)d_in[11];
    const float* w1      = (const float*)d_in[12];
    const float* b1      = (const float*)d_in[13];
    const float* w2      = (const float*)d_in[14];
    const float* b2      = (const float*)d_in[15];
    const float* lnf_g   = (const float*)d_in[16];
    const float* lnf_b   = (const float*)d_in[17];
    const float* lm_w    = (const float*)d_in[18];
    const float* lm_b    = (const float*)d_in[19];
    float* out = (float*)d_out;

    float *x, *h, *q, *k, *v, *att, *ff;
    cudaGetSymbolAddress((void**)&x,   g_x);
    cudaGetSymbolAddress((void**)&h,   g_h);
    cudaGetSymbolAddress((void**)&q,   g_q);
    cudaGetSymbolAddress((void**)&k,   g_k);
    cudaGetSymbolAddress((void**)&v,   g_v);
    cudaGetSymbolAddress((void**)&att, g_att);
    cudaGetSymbolAddress((void**)&ff,  g_ff);

    embed_kernel<<<MROWS, CC>>>(idx, tok_emb, pos_emb, x);

    for (int l = 0; l < LL; l++) {
        const float* wql = wq + (size_t)l * CC * CC;
        const float* wkl = wk + (size_t)l * CC * CC;
        const float* wvl = wv + (size_t)l * CC * CC;

        ln_kernel<<<MROWS, CC>>>(x, ln1_g + l*CC, ln1_b + l*CC, h);

        launch_gemm(h, wql, nullptr, nullptr, q, MROWS, CC, CC, 0);
        launch_gemm(h, wkl, nullptr, nullptr, k, MROWS, CC, CC, 0);
        launch_gemm(h, wvl, nullptr, nullptr, v, MROWS, CC, CC, 0);

        attn_kernel<<<BB*HH, TT>>>(q, k, v, att);

        // x = x + att @ proj_w + proj_b
        launch_gemm(att, proj_w + (size_t)l*CC*CC, proj_b + l*CC, x, x,
                    MROWS, CC, CC, 0);

        ln_kernel<<<MROWS, CC>>>(x, ln2_g + l*CC, ln2_b + l*CC, h);

        // ff = relu(h @ w1 + b1)
        launch_gemm(h, w1 + (size_t)l*CC*DFF, b1 + l*DFF, nullptr, ff,
                    MROWS, DFF, CC, 1);
        // x = x + ff @ w2 + b2
        launch_gemm(ff, w2 + (size_t)l*DFF*CC, b2 + l*CC, x, x,
                    MROWS, CC, DFF, 0);
    }

    ln_kernel<<<MROWS, CC>>>(x, lnf_g, lnf_b, h);

    // logits = h @ lm_w + lm_b
    launch_gemm(h, lm_w, lm_b, nullptr, out, MROWS, VV, CC, 0);
}

// round 5
// speedup vs baseline: 1.7503x; 1.7503x over previous
#include <cuda_runtime.h>
#include <cuda_bf16.h>
#include <math_constants.h>
#include <cstdint>

// Problem constants
#define BB 128
#define TT 128
#define CC 256
#define HH 4
#define LL 6
#define VV 10000
#define HS 64
#define DFF 1024
#define MROWS (BB*TT)   // 16384
#define VPAD 10112      // 79*128

// ---------------------------------------------------------------------------
// Scratch (device globals; no allocation allowed)
// ---------------------------------------------------------------------------
__device__ float g_x  [MROWS*CC];
__device__ float g_h  [MROWS*CC];
__device__ float g_q  [MROWS*CC];
__device__ float g_k  [MROWS*CC];
__device__ float g_v  [MROWS*CC];
__device__ float g_att[MROWS*CC];
__device__ float g_ff [MROWS*DFF];
// packed weights: bf16 hi/lo, [N,K] K-major
__device__ __nv_bfloat16 g_wqh[LL*CC*CC],  g_wql[LL*CC*CC];
__device__ __nv_bfloat16 g_wkh[LL*CC*CC],  g_wkl[LL*CC*CC];
__device__ __nv_bfloat16 g_wvh[LL*CC*CC],  g_wvl[LL*CC*CC];
__device__ __nv_bfloat16 g_pwh[LL*CC*CC],  g_pwl[LL*CC*CC];
__device__ __nv_bfloat16 g_w1h[LL*DFF*CC], g_w1l[LL*DFF*CC];
__device__ __nv_bfloat16 g_w2h[LL*CC*DFF], g_w2l[LL*CC*DFF];
__device__ __nv_bfloat16 g_lmh[VPAD*CC],   g_lml[VPAD*CC];

// ---------------------------------------------------------------------------
// HMMA m16n8k16 bf16 (row.col), fp32 accum
// ---------------------------------------------------------------------------
__device__ __forceinline__ void mma16816(float* d, const uint32_t* a, const uint32_t* b)
{
    asm volatile(
        "mma.sync.aligned.m16n8k16.row.col.f32.bf16.bf16.f32 "
        "{%0,%1,%2,%3}, {%4,%5,%6,%7}, {%8,%9}, {%0,%1,%2,%3};"
        : "+f"(d[0]), "+f"(d[1]), "+f"(d[2]), "+f"(d[3])
        : "r"(a[0]), "r"(a[1]), "r"(a[2]), "r"(a[3]), "r"(b[0]), "r"(b[1]));
}

// ---------------------------------------------------------------------------
// Weight prepack: W[K,N] fp32 -> Oh/Ol[NPAD,K] bf16 (hi/lo split), transposed.
// grid (NPAD/32, K/32), block (32,8)
// ---------------------------------------------------------------------------
__global__ void prep_kernel(const float* __restrict__ W,
                            __nv_bfloat16* __restrict__ Oh,
                            __nv_bfloat16* __restrict__ Ol, int K, int N)
{
    __shared__ float t[32][33];
    int nb = blockIdx.x * 32, kb = blockIdx.y * 32;
    int tx = threadIdx.x, ty = threadIdx.y;
    #pragma unroll
    for (int r = 0; r < 32; r += 8) {
        int k = kb + ty + r, n = nb + tx;
        t[ty + r][tx] = (n < N) ? W[(size_t)k * N + n] : 0.f;
    }
    __syncthreads();
    #pragma unroll
    for (int r = 0; r < 32; r += 8) {
        int n = nb + ty + r, k = kb + tx;
        float v = t[tx][ty + r];
        __nv_bfloat16 h = __float2bfloat16(v);
        __nv_bfloat16 l = __float2bfloat16(v - __bfloat162float(h));
        Oh[(size_t)n * K + k] = h;
        Ol[(size_t)n * K + k] = l;
    }
}

// ---------------------------------------------------------------------------
// Embedding
// ---------------------------------------------------------------------------
__global__ void embed_kernel(const int* __restrict__ idx,
                             const float* __restrict__ tok,
                             const float* __restrict__ pos,
                             float* __restrict__ x)
{
    int row = blockIdx.x;
    int tid = threadIdx.x;
    int token = idx[row];
    x[(size_t)row*CC + tid] = tok[(size_t)token*CC + tid] + pos[(row & (TT-1))*CC + tid];
}

// ---------------------------------------------------------------------------
// LayerNorm
// ---------------------------------------------------------------------------
__global__ void ln_kernel(const float* __restrict__ x,
                          const float* __restrict__ g,
                          const float* __restrict__ b,
                          float* __restrict__ out)
{
    int row = blockIdx.x;
    int tid = threadIdx.x;
    __shared__ float red[8];

    float v = x[(size_t)row*CC + tid];
    float s = v;
    #pragma unroll
    for (int o = 16; o; o >>= 1) s += __shfl_down_sync(0xffffffffu, s, o);
    if ((tid & 31) == 0) red[tid >> 5] = s;
    __syncthreads();
    if (tid < 8) {
        s = red[tid];
        #pragma unroll
        for (int o = 4; o; o >>= 1) s += __shfl_down_sync(0xffu, s, o);
        if (tid == 0) red[0] = s;
    }
    __syncthreads();
    float mean = red[0] * (1.f/CC);
    __syncthreads();

    float d = v - mean;
    float s2 = d * d;
    #pragma unroll
    for (int o = 16; o; o >>= 1) s2 += __shfl_down_sync(0xffffffffu, s2, o);
    if ((tid & 31) == 0) red[tid >> 5] = s2;
    __syncthreads();
    if (tid < 8) {
        s2 = red[tid];
        #pragma unroll
        for (int o = 4; o; o >>= 1) s2 += __shfl_down_sync(0xffu, s2, o);
        if (tid == 0) red[0] = s2;
    }
    __syncthreads();
    float var = red[0] * (1.f/CC);
    out[(size_t)row*CC + tid] = d * rsqrtf(var + 1e-5f) * g[tid] + b[tid];
}

// ---------------------------------------------------------------------------
// HMMA GEMM: C[M,N] = A[M,K](fp32) @ B[K,N] via bf16x3 split.
// B prepacked as Bh/Bl [NPAD,K] K-major bf16. Block tile 128x128x32,
// 8 warps (2 M x 4 N), warp tile 64x32, m16n8k16 atoms.
// Smem pitch 40 bf16/row (conflict-free fragment loads). Double buffered.
// ---------------------------------------------------------------------------
#define PITCH 40
#define TILE_E (128*PITCH)              // 5120 bf16 elements per array
#define BUF_E  (4*TILE_E)               // Ah, Al, Bh, Bl
#define GEMM_SMEM (2*BUF_E*2)           // bytes: 2 buffers * 20480 elem * 2B

__device__ __forceinline__ void load_tiles(
    __nv_bfloat16* sb,
    const float* __restrict__ A,
    const __nv_bfloat16* __restrict__ Bh, const __nv_bfloat16* __restrict__ Bl,
    int row0, int col0, int kt, int K, int tid)
{
    __nv_bfloat16* ah = sb;
    __nv_bfloat16* al = sb + TILE_E;
    __nv_bfloat16* bh = sb + 2*TILE_E;
    __nv_bfloat16* bl = sb + 3*TILE_E;

    // A: 128 rows x 32 fp32 -> hi/lo bf16
    #pragma unroll
    for (int it = 0; it < 4; it++) {
        int slot = tid + it*256;           // 0..1023 float4 slots
        int r = slot >> 3, c4 = (slot & 7) << 2;
        float4 a = *(const float4*)&A[(size_t)(row0 + r)*K + kt + c4];
        __nv_bfloat16 h0 = __float2bfloat16(a.x);
        __nv_bfloat16 h1 = __float2bfloat16(a.y);
        __nv_bfloat16 h2 = __float2bfloat16(a.z);
        __nv_bfloat16 h3 = __float2bfloat16(a.w);
        __nv_bfloat16 l0 = __float2bfloat16(a.x - __bfloat162float(h0));
        __nv_bfloat16 l1 = __float2bfloat16(a.y - __bfloat162float(h1));
        __nv_bfloat16 l2 = __float2bfloat16(a.z - __bfloat162float(h2));
        __nv_bfloat16 l3 = __float2bfloat16(a.w - __bfloat162float(h3));
        uint32_t ph0 = ((uint32_t)__bfloat16_as_ushort(h1) << 16) | __bfloat16_as_ushort(h0);
        uint32_t ph1 = ((uint32_t)__bfloat16_as_ushort(h3) << 16) | __bfloat16_as_ushort(h2);
        uint32_t pl0 = ((uint32_t)__bfloat16_as_ushort(l1) << 16) | __bfloat16_as_ushort(l0);
        uint32_t pl1 = ((uint32_t)__bfloat16_as_ushort(l3) << 16) | __bfloat16_as_ushort(l2);
        int e = r*PITCH + c4;
        *(uint32_t*)&ah[e]     = ph0;
        *(uint32_t*)&ah[e + 2] = ph1;
        *(uint32_t*)&al[e]     = pl0;
        *(uint32_t*)&al[e + 2] = pl1;
    }
    // B: 128 N-rows x 32 bf16 cols, 16B chunks
    #pragma unroll
    for (int it = 0; it < 2; it++) {
        int slot = tid + it*256;           // 0..511
        int r = slot >> 2, c8 = (slot & 3) << 3;
        int e = r*PITCH + c8;
        *(float4*)&bh[e] = *(const float4*)&Bh[(size_t)(col0 + r)*K + kt + c8];
        *(float4*)&bl[e] = *(const float4*)&Bl[(size_t)(col0 + r)*K + kt + c8];
    }
}

__global__ __launch_bounds__(256) void gemm_mma(
    const float* __restrict__ A,
    const __nv_bfloat16* __restrict__ Bh, const __nv_bfloat16* __restrict__ Bl,
    const float* __restrict__ bias, const float* __restrict__ resid,
    float* __restrict__ C, int M, int N, int K, int relu)
{
    extern __shared__ __nv_bfloat16 smem[];

    int tid  = threadIdx.x;
    int lane = tid & 31;
    int wid  = tid >> 5;
    int wm   = wid & 1;        // 2 warps across M (64 rows each)
    int wn   = wid >> 1;       // 4 warps across N (32 cols each)
    int g    = lane >> 2;      // 0..7
    int tg   = lane & 3;       // 0..3
    int row0 = blockIdx.y * 128;
    int col0 = blockIdx.x * 128;

    float acc[4][4][4];
    #pragma unroll
    for (int mi = 0; mi < 4; mi++)
        #pragma unroll
        for (int ni = 0; ni < 4; ni++)
            #pragma unroll
            for (int e = 0; e < 4; e++) acc[mi][ni][e] = 0.f;

    int nkb = K >> 5;
    load_tiles(smem, A, Bh, Bl, row0, col0, 0, K, tid);
    __syncthreads();

    for (int kb = 0; kb < nkb; kb++) {
        __nv_bfloat16* sb = smem + (kb & 1)*BUF_E;
        if (kb + 1 < nkb)
            load_tiles(smem + ((kb + 1) & 1)*BUF_E, A, Bh, Bl, row0, col0,
                       (kb + 1) << 5, K, tid);

        const __nv_bfloat16* ah = sb;
        const __nv_bfloat16* al = sb + TILE_E;
        const __nv_bfloat16* bhp = sb + 2*TILE_E;
        const __nv_bfloat16* blp = sb + 3*TILE_E;

        #pragma unroll
        for (int ks = 0; ks < 2; ks++) {
            int k0 = ks*16 + tg*2;
            // B fragments for this warp's 4 n8 tiles
            uint32_t fbh[4][2], fbl[4][2];
            #pragma unroll
            for (int ni = 0; ni < 4; ni++) {
                int n = wn*32 + ni*8 + g;
                fbh[ni][0] = *(const uint32_t*)&bhp[n*PITCH + k0];
                fbh[ni][1] = *(const uint32_t*)&bhp[n*PITCH + k0 + 8];
                fbl[ni][0] = *(const uint32_t*)&blp[n*PITCH + k0];
                fbl[ni][1] = *(const uint32_t*)&blp[n*PITCH + k0 + 8];
            }
            #pragma unroll
            for (int mi = 0; mi < 4; mi++) {
                int m = wm*64 + mi*16 + g;
                uint32_t fah[4], fal[4];
                fah[0] = *(const uint32_t*)&ah[m*PITCH + k0];
                fah[1] = *(const uint32_t*)&ah[(m+8)*PITCH + k0];
                fah[2] = *(const uint32_t*)&ah[m*PITCH + k0 + 8];
                fah[3] = *(const uint32_t*)&ah[(m+8)*PITCH + k0 + 8];
                fal[0] = *(const uint32_t*)&al[m*PITCH + k0];
                fal[1] = *(const uint32_t*)&al[(m+8)*PITCH + k0];
                fal[2] = *(const uint32_t*)&al[m*PITCH + k0 + 8];
                fal[3] = *(const uint32_t*)&al[(m+8)*PITCH + k0 + 8];
                #pragma unroll
                for (int ni = 0; ni < 4; ni++) {
                    mma16816(acc[mi][ni], fah, fbh[ni]);
                    mma16816(acc[mi][ni], fah, fbl[ni]);
                    mma16816(acc[mi][ni], fal, fbh[ni]);
                }
            }
        }
        __syncthreads();
    }

    // Epilogue: write accumulators (float2 per frag-row), fused bias/resid/relu
    #pragma unroll
    for (int mi = 0; mi < 4; mi++) {
        #pragma unroll
        for (int r2 = 0; r2 < 2; r2++) {
            int grow = row0 + wm*64 + mi*16 + g + r2*8;
            #pragma unroll
            for (int ni = 0; ni < 4; ni++) {
                int c = col0 + wn*32 + ni*8 + tg*2;
                if (c < N) {
                    float v0 = acc[mi][ni][r2*2];
                    float v1 = acc[mi][ni][r2*2 + 1];
                    if (bias)  { v0 += bias[c]; v1 += bias[c+1]; }
                    if (resid) {
                        float2 rr = *(const float2*)&resid[(size_t)grow*N + c];
                        v0 += rr.x; v1 += rr.y;
                    }
                    if (relu) { v0 = fmaxf(v0, 0.f); v1 = fmaxf(v1, 0.f); }
                    float2 o; o.x = v0; o.y = v1;
                    *(float2*)&C[(size_t)grow*N + c] = o;
                }
            }
        }
    }
}

// ---------------------------------------------------------------------------
// Attention: block per (b,h), thread = query row, online softmax.
// ---------------------------------------------------------------------------
__global__ __launch_bounds__(128) void attn_kernel(
    const float* __restrict__ Q, const float* __restrict__ K,
    const float* __restrict__ V, float* __restrict__ O)
{
    __shared__ float ks[64][64];
    __shared__ float vs[64][64];

    int bh = blockIdx.x;
    int b  = bh >> 2;
    int h  = bh & 3;
    int t  = threadIdx.x;
    const float scale = 0.0625f;

    const float* qp = Q + (((size_t)b*TT + t)*HH + h)*HS;
    float q[HS];
    #pragma unroll
    for (int d = 0; d < HS; d++) q[d] = qp[d] * scale;

    float m = -CUDART_INF_F;
    float s = 0.f;
    float acc[HS];
    #pragma unroll
    for (int d = 0; d < HS; d++) acc[d] = 0.f;

    for (int kc = 0; kc < TT; kc += 64) {
        __syncthreads();
        for (int i = t; i < 64*16; i += 128) {
            int r = i >> 4;
            int c = (i & 15) * 4;
            size_t goff = (((size_t)b*TT + kc + r)*HH + h)*HS + c;
            *(float4*)&ks[r][c] = *(const float4*)&K[goff];
            *(float4*)&vs[r][c] = *(const float4*)&V[goff];
        }
        __syncthreads();

        int jmax = t - kc + 1;
        if (jmax > 64) jmax = 64;
        for (int j = 0; j < jmax; j++) {
            float sc = 0.f;
            #pragma unroll
            for (int d = 0; d < HS; d++) sc += q[d] * ks[j][d];
            float nm = fmaxf(m, sc);
            float f  = __expf(m  - nm);
            float e  = __expf(sc - nm);
            s = s * f + e;
            #pragma unroll
            for (int d = 0; d < HS; d++) acc[d] = acc[d] * f + e * vs[j][d];
            m = nm;
        }
    }

    float inv = 1.f / s;
    float* op = O + (((size_t)b*TT + t)*HH + h)*HS;
    #pragma unroll
    for (int d = 0; d < HS; d++) op[d] = acc[d] * inv;
}

// ---------------------------------------------------------------------------
// Launch
// ---------------------------------------------------------------------------
static inline void launch_gemm_tc(const float* A, const __nv_bfloat16* Bh,
                                  const __nv_bfloat16* Bl, const float* bias,
                                  const float* resid, float* C,
                                  int M, int N, int NPAD, int K, int relu)
{
    dim3 grid(NPAD / 128, M / 128);
    gemm_mma<<<grid, 256, GEMM_SMEM>>>(A, Bh, Bl, bias, resid, C, M, N, K, relu);
}

extern "C" void kernel_launch(void* const* d_in, const int* in_sizes, int n_in,
                              void* d_out, int out_size)
{
    const int*   idx     = (const int*)  d_in[0];
    const float* tok_emb = (const float*)d_in[1];
    const float* pos_emb = (const float*)d_in[2];
    const float* ln1_g   = (const float*)d_in[3];
    const float* ln1_b   = (const float*)d_in[4];
    const float* wq      = (const float*)d_in[5];
    const float* wk      = (const float*)d_in[6];
    const float* wv      = (const float*)d_in[7];
    const float* proj_w  = (const float*)d_in[8];
    const float* proj_b  = (const float*)d_in[9];
    const float* ln2_g   = (const float*)d_in[10];
    const float* ln2_b   = (const float*)d_in[11];
    const float* w1      = (const float*)d_in[12];
    const float* b1      = (const float*)d_in[13];
    const float* w2      = (const float*)d_in[14];
    const float* b2      = (const float*)d_in[15];
    const float* lnf_g   = (const float*)d_in[16];
    const float* lnf_b   = (const float*)d_in[17];
    const float* lm_w    = (const float*)d_in[18];
    const float* lm_b    = (const float*)d_in[19];
    float* out = (float*)d_out;

    cudaFuncSetAttribute(gemm_mma, cudaFuncAttributeMaxDynamicSharedMemorySize, GEMM_SMEM);

    float *x, *h, *q, *k, *v, *att, *ff;
    cudaGetSymbolAddress((void**)&x,   g_x);
    cudaGetSymbolAddress((void**)&h,   g_h);
    cudaGetSymbolAddress((void**)&q,   g_q);
    cudaGetSymbolAddress((void**)&k,   g_k);
    cudaGetSymbolAddress((void**)&v,   g_v);
    cudaGetSymbolAddress((void**)&att, g_att);
    cudaGetSymbolAddress((void**)&ff,  g_ff);

    __nv_bfloat16 *wqh,*wql,*wkh,*wkl,*wvh,*wvl,*pwh,*pwl,*w1h,*w1l,*w2h,*w2l,*lmh,*lml;
    cudaGetSymbolAddress((void**)&wqh, g_wqh); cudaGetSymbolAddress((void**)&wql, g_wql);
    cudaGetSymbolAddress((void**)&wkh, g_wkh); cudaGetSymbolAddress((void**)&wkl, g_wkl);
    cudaGetSymbolAddress((void**)&wvh, g_wvh); cudaGetSymbolAddress((void**)&wvl, g_wvl);
    cudaGetSymbolAddress((void**)&pwh, g_pwh); cudaGetSymbolAddress((void**)&pwl, g_pwl);
    cudaGetSymbolAddress((void**)&w1h, g_w1h); cudaGetSymbolAddress((void**)&w1l, g_w1l);
    cudaGetSymbolAddress((void**)&w2h, g_w2h); cudaGetSymbolAddress((void**)&w2l, g_w2l);
    cudaGetSymbolAddress((void**)&lmh, g_lmh); cudaGetSymbolAddress((void**)&lml, g_lml);

    // ---- prepack weights (transpose + bf16 hi/lo split) ----
    dim3 pb(32, 8);
    for (int l = 0; l < LL; l++) {
        prep_kernel<<<dim3(CC/32, CC/32),  pb>>>(wq     + (size_t)l*CC*CC,  wqh + (size_t)l*CC*CC,  wql + (size_t)l*CC*CC,  CC, CC);
        prep_kernel<<<dim3(CC/32, CC/32),  pb>>>(wk     + (size_t)l*CC*CC,  wkh + (size_t)l*CC*CC,  wkl + (size_t)l*CC*CC,  CC, CC);
        prep_kernel<<<dim3(CC/32, CC/32),  pb>>>(wv     + (size_t)l*CC*CC,  wvh + (size_t)l*CC*CC,  wvl + (size_t)l*CC*CC,  CC, CC);
        prep_kernel<<<dim3(CC/32, CC/32),  pb>>>(proj_w + (size_t)l*CC*CC,  pwh + (size_t)l*CC*CC,  pwl + (size_t)l*CC*CC,  CC, CC);
        prep_kernel<<<dim3(DFF/32, CC/32), pb>>>(w1     + (size_t)l*CC*DFF, w1h + (size_t)l*DFF*CC, w1l + (size_t)l*DFF*CC, CC, DFF);
        prep_kernel<<<dim3(CC/32, DFF/32), pb>>>(w2     + (size_t)l*DFF*CC, w2h + (size_t)l*CC*DFF, w2l + (size_t)l*CC*DFF, DFF, CC);
    }
    prep_kernel<<<dim3(VPAD/32, CC/32), pb>>>(lm_w, lmh, lml, CC, VV);

    // ---- forward ----
    embed_kernel<<<MROWS, CC>>>(idx, tok_emb, pos_emb, x);

    for (int l = 0; l < LL; l++) {
        ln_kernel<<<MROWS, CC>>>(x, ln1_g + l*CC, ln1_b + l*CC, h);

        launch_gemm_tc(h, wqh + (size_t)l*CC*CC, wql + (size_t)l*CC*CC, nullptr, nullptr, q, MROWS, CC, CC, CC, 0);
        launch_gemm_tc(h, wkh + (size_t)l*CC*CC, wkl + (size_t)l*CC*CC, nullptr, nullptr, k, MROWS, CC, CC, CC, 0);
        launch_gemm_tc(h, wvh + (size_t)l*CC*CC, wvl + (size_t)l*CC*CC, nullptr, nullptr, v, MROWS, CC, CC, CC, 0);

        attn_kernel<<<BB*HH, TT>>>(q, k, v, att);

        launch_gemm_tc(att, pwh + (size_t)l*CC*CC, pwl + (size_t)l*CC*CC, proj_b + l*CC, x, x, MROWS, CC, CC, CC, 0);

        ln_kernel<<<MROWS, CC>>>(x, ln2_g + l*CC, ln2_b + l*CC, h);

        launch_gemm_tc(h,  w1h + (size_t)l*DFF*CC, w1l + (size_t)l*DFF*CC, b1 + l*DFF, nullptr, ff, MROWS, DFF, DFF, CC, 1);
        launch_gemm_tc(ff, w2h + (size_t)l*CC*DFF, w2l + (size_t)l*CC*DFF, b2 + l*CC, x, x, MROWS, CC, CC, DFF, 0);
    }

    ln_kernel<<<MROWS, CC>>>(x, lnf_g, lnf_b, h);

    launch_gemm_tc(h, lmh, lml, lm_b, nullptr, out, MROWS, VV, VPAD, CC, 0);
}

// round 6
// speedup vs baseline: 2.0535x; 1.1732x over previous
#include <cuda_runtime.h>
#include <cuda_bf16.h>
#include <math_constants.h>
#include <cstdint>

// Problem constants
#define BB 128
#define TT 128
#define CC 256
#define HH 4
#define LL 6
#define VV 10000
#define HS 64
#define DFF 1024
#define MROWS (BB*TT)   // 16384
#define VPAD 10112      // 79*128
#define NQKV 768

// ---------------------------------------------------------------------------
// Scratch (device globals; no allocation allowed)
// ---------------------------------------------------------------------------
__device__ float g_x  [MROWS*CC];        // residual stream (fp32)
__device__ float g_qkv[MROWS*NQKV];      // fused qkv output (fp32)
__device__ __nv_bfloat16 g_hh[MROWS*CC],  g_hl[MROWS*CC];    // LN out hi/lo
__device__ __nv_bfloat16 g_ath[MROWS*CC], g_atl[MROWS*CC];   // attn out hi/lo
__device__ __nv_bfloat16 g_ffh[MROWS*DFF], g_ffl[MROWS*DFF]; // MLP hidden hi/lo
// packed weights: bf16 hi/lo, [N,K] K-major
__device__ __nv_bfloat16 g_qkvh[LL*NQKV*CC], g_qkvl[LL*NQKV*CC];
__device__ __nv_bfloat16 g_pwh[LL*CC*CC],  g_pwl[LL*CC*CC];
__device__ __nv_bfloat16 g_w1h[LL*DFF*CC], g_w1l[LL*DFF*CC];
__device__ __nv_bfloat16 g_w2h[LL*CC*DFF], g_w2l[LL*CC*DFF];
__device__ __nv_bfloat16 g_lmh[VPAD*CC],   g_lml[VPAD*CC];

// ---------------------------------------------------------------------------
// PTX primitives (all valid on plain compute_103)
// ---------------------------------------------------------------------------
__device__ __forceinline__ void mma16816(float* d, const uint32_t* a, const uint32_t* b)
{
    asm volatile(
        "mma.sync.aligned.m16n8k16.row.col.f32.bf16.bf16.f32 "
        "{%0,%1,%2,%3}, {%4,%5,%6,%7}, {%8,%9}, {%0,%1,%2,%3};"
        : "+f"(d[0]), "+f"(d[1]), "+f"(d[2]), "+f"(d[3])
        : "r"(a[0]), "r"(a[1]), "r"(a[2]), "r"(a[3]), "r"(b[0]), "r"(b[1]));
}
__device__ __forceinline__ void ldsm_x4(uint32_t* r, uint32_t addr)
{
    asm volatile("ldmatrix.sync.aligned.m8n8.x4.shared.b16 {%0,%1,%2,%3}, [%4];"
        : "=r"(r[0]), "=r"(r[1]), "=r"(r[2]), "=r"(r[3]) : "r"(addr));
}
__device__ __forceinline__ uint32_t smem_u32(const void* p) {
    uint32_t a;
    asm("{ .reg .u64 t; cvta.to.shared.u64 t, %1; cvt.u32.u64 %0, t; }" : "=r"(a) : "l"(p));
    return a;
}
#define CP16(dst, src) \
    asm volatile("cp.async.cg.shared.global [%0], [%1], 16;" :: "r"(dst), "l"(src))
#define CP_COMMIT() asm volatile("cp.async.commit_group;" ::: "memory")
#define CP_WAIT(n)  asm volatile("cp.async.wait_group %0;" :: "n"(n) : "memory")

__device__ __forceinline__ void split_bf16(float v, __nv_bfloat16& h, __nv_bfloat16& l)
{
    h = __float2bfloat16(v);
    l = __float2bfloat16(v - __bfloat162float(h));
}

// ---------------------------------------------------------------------------
// Weight prepack: W[L][K][N] fp32 -> Oh/Ol[L][NPAD][K] bf16 hi/lo, transposed.
// grid (NPAD/32, K/32, L), block (32,8)
// ---------------------------------------------------------------------------
__global__ void prep_kernel(const float* __restrict__ W,
                            __nv_bfloat16* __restrict__ Oh,
                            __nv_bfloat16* __restrict__ Ol,
                            int K, int N, size_t wstride, size_t ostride)
{
    __shared__ float t[32][33];
    W  += blockIdx.z * wstride;
    Oh += blockIdx.z * ostride;
    Ol += blockIdx.z * ostride;
    int nb = blockIdx.x * 32, kb = blockIdx.y * 32;
    int tx = threadIdx.x, ty = threadIdx.y;
    #pragma unroll
    for (int r = 0; r < 32; r += 8) {
        int k = kb + ty + r, n = nb + tx;
        t[ty + r][tx] = (n < N) ? W[(size_t)k * N + n] : 0.f;
    }
    __syncthreads();
    #pragma unroll
    for (int r = 0; r < 32; r += 8) {
        int n = nb + ty + r, k = kb + tx;
        float v = t[tx][ty + r];
        __nv_bfloat16 h, l;
        split_bf16(v, h, l);
        Oh[(size_t)n * K + k] = h;
        Ol[(size_t)n * K + k] = l;
    }
}

// ---------------------------------------------------------------------------
// Embedding
// ---------------------------------------------------------------------------
__global__ void embed_kernel(const int* __restrict__ idx,
                             const float* __restrict__ tok,
                             const float* __restrict__ pos,
                             float* __restrict__ x)
{
    int row = blockIdx.x;
    int tid = threadIdx.x;
    int token = idx[row];
    x[(size_t)row*CC + tid] = tok[(size_t)token*CC + tid] + pos[(row & (TT-1))*CC + tid];
}

// ---------------------------------------------------------------------------
// LayerNorm -> bf16 hi/lo split output
// ---------------------------------------------------------------------------
__global__ void ln_kernel(const float* __restrict__ x,
                          const float* __restrict__ g,
                          const float* __restrict__ b,
                          __nv_bfloat16* __restrict__ oh,
                          __nv_bfloat16* __restrict__ ol)
{
    int row = blockIdx.x;
    int tid = threadIdx.x;
    __shared__ float red[8];

    float v = x[(size_t)row*CC + tid];
    float s = v;
    #pragma unroll
    for (int o = 16; o; o >>= 1) s += __shfl_down_sync(0xffffffffu, s, o);
    if ((tid & 31) == 0) red[tid >> 5] = s;
    __syncthreads();
    if (tid < 8) {
        s = red[tid];
        #pragma unroll
        for (int o = 4; o; o >>= 1) s += __shfl_down_sync(0xffu, s, o);
        if (tid == 0) red[0] = s;
    }
    __syncthreads();
    float mean = red[0] * (1.f/CC);
    __syncthreads();

    float d = v - mean;
    float s2 = d * d;
    #pragma unroll
    for (int o = 16; o; o >>= 1) s2 += __shfl_down_sync(0xffffffffu, s2, o);
    if ((tid & 31) == 0) red[tid >> 5] = s2;
    __syncthreads();
    if (tid < 8) {
        s2 = red[tid];
        #pragma unroll
        for (int o = 4; o; o >>= 1) s2 += __shfl_down_sync(0xffu, s2, o);
        if (tid == 0) red[0] = s2;
    }
    __syncthreads();
    float var = red[0] * (1.f/CC);
    float y = d * rsqrtf(var + 1e-5f) * g[tid] + b[tid];
    __nv_bfloat16 hh, ll;
    split_bf16(y, hh, ll);
    oh[(size_t)row*CC + tid] = hh;
    ol[(size_t)row*CC + tid] = ll;
}

// ---------------------------------------------------------------------------
// HMMA GEMM: C[M,N] = (Ah+Al)[M,K] @ (Bh+Bl)[K,N] via 3-term split.
// A,B prepacked bf16 hi/lo, K-major. Block tile 128x128x32, 8 warps (2Mx4N),
// warp tile 64x32, m16n8k16, ldmatrix fragments, cp.async double buffering.
// Output: fp32 (bias/resid/relu) OR bf16 hi/lo split (bias/relu).
// ---------------------------------------------------------------------------
#define PITCH 40
#define TILE_B (128*PITCH*2)            // bytes per tile array (10240)
#define BUF_B  (4*TILE_B)               // Ah, Al, Bh, Bl (40960)
#define GEMM_SMEM (2*BUF_B)             // 81920

__device__ __forceinline__ void load_tiles_async(
    uint32_t sdst,
    const __nv_bfloat16* __restrict__ Ah, const __nv_bfloat16* __restrict__ Al,
    const __nv_bfloat16* __restrict__ Bh, const __nv_bfloat16* __restrict__ Bl,
    int row0, int col0, int kt, int K, int tid)
{
    #pragma unroll
    for (int half = 0; half < 2; half++) {
        int slot = tid + half*256;
        int r = slot >> 2, c8 = (slot & 3) << 3;
        uint32_t doff = (uint32_t)(r*PITCH + c8)*2;
        size_t ga = (size_t)(row0 + r)*K + kt + c8;
        size_t gb = (size_t)(col0 + r)*K + kt + c8;
        CP16(sdst + 0*TILE_B + doff, Ah + ga);
        CP16(sdst + 1*TILE_B + doff, Al + ga);
        CP16(sdst + 2*TILE_B + doff, Bh + gb);
        CP16(sdst + 3*TILE_B + doff, Bl + gb);
    }
}

__global__ __launch_bounds__(256) void gemm_mma(
    const __nv_bfloat16* __restrict__ Ah, const __nv_bfloat16* __restrict__ Al,
    const __nv_bfloat16* __restrict__ Bh, const __nv_bfloat16* __restrict__ Bl,
    const float* __restrict__ bias, const float* __restrict__ resid,
    float* __restrict__ C,
    __nv_bfloat16* __restrict__ Ch, __nv_bfloat16* __restrict__ Cl,
    int M, int N, int K, int relu)
{
    extern __shared__ char smem[];
    uint32_t s0 = smem_u32(smem);

    int tid  = threadIdx.x;
    int lane = tid & 31;
    int wid  = tid >> 5;
    int wm   = wid & 1;        // 2 warps across M (64 rows each)
    int wn   = wid >> 1;       // 4 warps across N (32 cols each)
    int g    = lane >> 2;
    int tg   = lane & 3;
    int row0 = blockIdx.y * 128;
    int col0 = blockIdx.x * 128;

    // ldmatrix per-lane base offsets (bytes)
    uint32_t a_lane = (uint32_t)((wm*64 + (lane & 7) + ((lane >> 3) & 1)*8)*PITCH
                                 + (lane >> 4)*8) * 2;
    uint32_t b_lane = (uint32_t)((wn*32 + (lane & 7) + ((lane >> 4) & 1)*8)*PITCH
                                 + ((lane >> 3) & 1)*8) * 2;

    float acc[4][4][4];
    #pragma unroll
    for (int mi = 0; mi < 4; mi++)
        #pragma unroll
        for (int ni = 0; ni < 4; ni++)
            #pragma unroll
            for (int e = 0; e < 4; e++) acc[mi][ni][e] = 0.f;

    int nkb = K >> 5;
    load_tiles_async(s0, Ah, Al, Bh, Bl, row0, col0, 0, K, tid);
    CP_COMMIT();

    for (int kb = 0; kb < nkb; kb++) {
        if (kb + 1 < nkb) {
            load_tiles_async(s0 + ((kb + 1) & 1)*BUF_B, Ah, Al, Bh, Bl,
                             row0, col0, (kb + 1) << 5, K, tid);
            CP_COMMIT();
            CP_WAIT(1);
        } else {
            CP_WAIT(0);
        }
        __syncthreads();

        uint32_t bufb = s0 + (kb & 1)*BUF_B;
        #pragma unroll
        for (int ks = 0; ks < 2; ks++) {
            // B fragments: [hi/lo][ni][2]
            uint32_t tb[4];
            uint32_t fbh[4][2], fbl[4][2];
            ldsm_x4(tb, bufb + 2*TILE_B + b_lane + ks*32);
            fbh[0][0]=tb[0]; fbh[0][1]=tb[1]; fbh[1][0]=tb[2]; fbh[1][1]=tb[3];
            ldsm_x4(tb, bufb + 2*TILE_B + b_lane + 16*PITCH*2 + ks*32);
            fbh[2][0]=tb[0]; fbh[2][1]=tb[1]; fbh[3][0]=tb[2]; fbh[3][1]=tb[3];
            ldsm_x4(tb, bufb + 3*TILE_B + b_lane + ks*32);
            fbl[0][0]=tb[0]; fbl[0][1]=tb[1]; fbl[1][0]=tb[2]; fbl[1][1]=tb[3];
            ldsm_x4(tb, bufb + 3*TILE_B + b_lane + 16*PITCH*2 + ks*32);
            fbl[2][0]=tb[0]; fbl[2][1]=tb[1]; fbl[3][0]=tb[2]; fbl[3][1]=tb[3];

            #pragma unroll
            for (int mi = 0; mi < 4; mi++) {
                uint32_t fah[4], fal[4];
                uint32_t ao = a_lane + (uint32_t)(mi*16*PITCH*2) + ks*32;
                ldsm_x4(fah, bufb + 0*TILE_B + ao);
                ldsm_x4(fal, bufb + 1*TILE_B + ao);
                #pragma unroll
                for (int ni = 0; ni < 4; ni++) {
                    mma16816(acc[mi][ni], fah, fbh[ni]);
                    mma16816(acc[mi][ni], fah, fbl[ni]);
                    mma16816(acc[mi][ni], fal, fbh[ni]);
                }
            }
        }
        __syncthreads();
    }

    // Epilogue
    #pragma unroll
    for (int mi = 0; mi < 4; mi++) {
        #pragma unroll
        for (int r2 = 0; r2 < 2; r2++) {
            int grow = row0 + wm*64 + mi*16 + g + r2*8;
            #pragma unroll
            for (int ni = 0; ni < 4; ni++) {
                int c = col0 + wn*32 + ni*8 + tg*2;
                float v0 = acc[mi][ni][r2*2];
                float v1 = acc[mi][ni][r2*2 + 1];
                if (bias)  { v0 += bias[c]; v1 += bias[c+1]; }
                if (relu)  { v0 = fmaxf(v0, 0.f); v1 = fmaxf(v1, 0.f); }
                if (C) {
                    if (c < N) {
                        if (resid) {
                            float2 rr = *(const float2*)&resid[(size_t)grow*N + c];
                            v0 += rr.x; v1 += rr.y;
                        }
                        float2 o; o.x = v0; o.y = v1;
                        *(float2*)&C[(size_t)grow*N + c] = o;
                    }
                } else {
                    __nv_bfloat16 h0, l0, h1, l1;
                    split_bf16(v0, h0, l0);
                    split_bf16(v1, h1, l1);
                    uint32_t ph = ((uint32_t)__bfloat16_as_ushort(h1) << 16) | __bfloat16_as_ushort(h0);
                    uint32_t pl = ((uint32_t)__bfloat16_as_ushort(l1) << 16) | __bfloat16_as_ushort(l0);
                    *(uint32_t*)&Ch[(size_t)grow*N + c] = ph;
                    *(uint32_t*)&Cl[(size_t)grow*N + c] = pl;
                }
            }
        }
    }
}

// ---------------------------------------------------------------------------
// Attention: block per (b,h), thread = query row, online softmax.
// QKV fused input [M, 768] fp32 (q:0..255, k:256..511, v:512..767).
// Output: bf16 hi/lo split att [M, 256].
// ---------------------------------------------------------------------------
__global__ __launch_bounds__(128) void attn_kernel(
    const float* __restrict__ QKV,
    __nv_bfloat16* __restrict__ Oh, __nv_bfloat16* __restrict__ Ol)
{
    __shared__ float ks[64][64];
    __shared__ float vs[64][64];

    int bh = blockIdx.x;
    int b  = bh >> 2;
    int h  = bh & 3;
    int t  = threadIdx.x;
    const float scale = 0.0625f;

    const float* qp = QKV + ((size_t)b*TT + t)*NQKV + h*HS;
    float q[HS];
    #pragma unroll
    for (int d = 0; d < HS; d++) q[d] = qp[d] * scale;

    float m = -CUDART_INF_F;
    float s = 0.f;
    float acc[HS];
    #pragma unroll
    for (int d = 0; d < HS; d++) acc[d] = 0.f;

    for (int kc = 0; kc < TT; kc += 64) {
        __syncthreads();
        for (int i = t; i < 64*16; i += 128) {
            int r = i >> 4;
            int c = (i & 15) * 4;
            size_t go = ((size_t)b*TT + kc + r)*NQKV + h*HS + c;
            *(float4*)&ks[r][c] = *(const float4*)&QKV[go + 256];
            *(float4*)&vs[r][c] = *(const float4*)&QKV[go + 512];
        }
        __syncthreads();

        int jmax = t - kc + 1;
        if (jmax > 64) jmax = 64;
        for (int j = 0; j < jmax; j++) {
            float sc = 0.f;
            #pragma unroll
            for (int d = 0; d < HS; d++) sc += q[d] * ks[j][d];
            float nm = fmaxf(m, sc);
            float f  = __expf(m  - nm);
            float e  = __expf(sc - nm);
            s = s * f + e;
            #pragma unroll
            for (int d = 0; d < HS; d++) acc[d] = acc[d] * f + e * vs[j][d];
            m = nm;
        }
    }

    float inv = 1.f / s;
    size_t oo = ((size_t)b*TT + t)*CC + h*HS;
    #pragma unroll
    for (int d = 0; d < HS; d++) {
        float o = acc[d] * inv;
        __nv_bfloat16 hh, ll;
        split_bf16(o, hh, ll);
        Oh[oo + d] = hh;
        Ol[oo + d] = ll;
    }
}

// ---------------------------------------------------------------------------
// Launch helpers
// ---------------------------------------------------------------------------
static inline void launch_gemm(const __nv_bfloat16* Ah, const __nv_bfloat16* Al,
                               const __nv_bfloat16* Bh, const __nv_bfloat16* Bl,
                               const float* bias, const float* resid,
                               float* C, __nv_bfloat16* Ch, __nv_bfloat16* Cl,
                               int M, int N, int NPAD, int K, int relu)
{
    dim3 grid(NPAD / 128, M / 128);
    gemm_mma<<<grid, 256, GEMM_SMEM>>>(Ah, Al, Bh, Bl, bias, resid, C, Ch, Cl,
                                       M, N, K, relu);
}

extern "C" void kernel_launch(void* const* d_in, const int* in_sizes, int n_in,
                              void* d_out, int out_size)
{
    const int*   idx     = (const int*)  d_in[0];
    const float* tok_emb = (const float*)d_in[1];
    const float* pos_emb = (const float*)d_in[2];
    const float* ln1_g   = (const float*)d_in[3];
    const float* ln1_b   = (const float*)d_in[4];
    const float* wq      = (const float*)d_in[5];
    const float* wk      = (const float*)d_in[6];
    const float* wv      = (const float*)d_in[7];
    const float* proj_w  = (const float*)d_in[8];
    const float* proj_b  = (const float*)d_in[9];
    const float* ln2_g   = (const float*)d_in[10];
    const float* ln2_b   = (const float*)d_in[11];
    const float* w1      = (const float*)d_in[12];
    const float* b1      = (const float*)d_in[13];
    const float* w2      = (const float*)d_in[14];
    const float* b2      = (const float*)d_in[15];
    const float* lnf_g   = (const float*)d_in[16];
    const float* lnf_b   = (const float*)d_in[17];
    const float* lm_w    = (const float*)d_in[18];
    const float* lm_b    = (const float*)d_in[19];
    float* out = (float*)d_out;

    cudaFuncSetAttribute(gemm_mma, cudaFuncAttributeMaxDynamicSharedMemorySize, GEMM_SMEM);

    float *x, *qkv;
    cudaGetSymbolAddress((void**)&x,   g_x);
    cudaGetSymbolAddress((void**)&qkv, g_qkv);
    __nv_bfloat16 *hh,*hl,*ath,*atl,*ffh,*ffl;
    cudaGetSymbolAddress((void**)&hh,  g_hh);  cudaGetSymbolAddress((void**)&hl,  g_hl);
    cudaGetSymbolAddress((void**)&ath, g_ath); cudaGetSymbolAddress((void**)&atl, g_atl);
    cudaGetSymbolAddress((void**)&ffh, g_ffh); cudaGetSymbolAddress((void**)&ffl, g_ffl);
    __nv_bfloat16 *qkvh,*qkvl,*pwh,*pwl,*w1h,*w1l,*w2h,*w2l,*lmh,*lml;
    cudaGetSymbolAddress((void**)&qkvh, g_qkvh); cudaGetSymbolAddress((void**)&qkvl, g_qkvl);
    cudaGetSymbolAddress((void**)&pwh,  g_pwh);  cudaGetSymbolAddress((void**)&pwl,  g_pwl);
    cudaGetSymbolAddress((void**)&w1h,  g_w1h);  cudaGetSymbolAddress((void**)&w1l,  g_w1l);
    cudaGetSymbolAddress((void**)&w2h,  g_w2h);  cudaGetSymbolAddress((void**)&w2l,  g_w2l);
    cudaGetSymbolAddress((void**)&lmh,  g_lmh);  cudaGetSymbolAddress((void**)&lml,  g_lml);

    // ---- prepack weights (batched over layers via gridDim.z) ----
    dim3 pb(32, 8);
    // qkv sections: rows 0-255 = wq', 256-511 = wk', 512-767 = wv'
    prep_kernel<<<dim3(CC/32, CC/32, LL),  pb>>>(wq,     qkvh + 0*CC*CC, qkvl + 0*CC*CC, CC, CC, (size_t)CC*CC, (size_t)NQKV*CC);
    prep_kernel<<<dim3(CC/32, CC/32, LL),  pb>>>(wk,     qkvh + 1*CC*CC, qkvl + 1*CC*CC, CC, CC, (size_t)CC*CC, (size_t)NQKV*CC);
    prep_kernel<<<dim3(CC/32, CC/32, LL),  pb>>>(wv,     qkvh + 2*CC*CC, qkvl + 2*CC*CC, CC, CC, (size_t)CC*CC, (size_t)NQKV*CC);
    prep_kernel<<<dim3(CC/32, CC/32, LL),  pb>>>(proj_w, pwh, pwl, CC, CC,  (size_t)CC*CC,  (size_t)CC*CC);
    prep_kernel<<<dim3(DFF/32, CC/32, LL), pb>>>(w1,     w1h, w1l, CC, DFF, (size_t)CC*DFF, (size_t)DFF*CC);
    prep_kernel<<<dim3(CC/32, DFF/32, LL), pb>>>(w2,     w2h, w2l, DFF, CC, (size_t)DFF*CC, (size_t)CC*DFF);
    prep_kernel<<<dim3(VPAD/32, CC/32, 1), pb>>>(lm_w,   lmh, lml, CC, VV, 0, 0);

    // ---- forward ----
    embed_kernel<<<MROWS, CC>>>(idx, tok_emb, pos_emb, x);

    for (int l = 0; l < LL; l++) {
        ln_kernel<<<MROWS, CC>>>(x, ln1_g + l*CC, ln1_b + l*CC, hh, hl);

        // fused QKV: [M, 768] fp32
        launch_gemm(hh, hl, qkvh + (size_t)l*NQKV*CC, qkvl + (size_t)l*NQKV*CC,
                    nullptr, nullptr, qkv, nullptr, nullptr,
                    MROWS, NQKV, NQKV, CC, 0);

        attn_kernel<<<BB*HH, TT>>>(qkv, ath, atl);

        // x = x + att @ proj_w + proj_b
        launch_gemm(ath, atl, pwh + (size_t)l*CC*CC, pwl + (size_t)l*CC*CC,
                    proj_b + l*CC, x, x, nullptr, nullptr,
                    MROWS, CC, CC, CC, 0);

        ln_kernel<<<MROWS, CC>>>(x, ln2_g + l*CC, ln2_b + l*CC, hh, hl);

        // ff = relu(h @ w1 + b1) -> bf16 hi/lo
        launch_gemm(hh, hl, w1h + (size_t)l*DFF*CC, w1l + (size_t)l*DFF*CC,
                    b1 + l*DFF, nullptr, nullptr, ffh, ffl,
                    MROWS, DFF, DFF, CC, 1);

        // x = x + ff @ w2 + b2
        launch_gemm(ffh, ffl, w2h + (size_t)l*CC*DFF, w2l + (size_t)l*CC*DFF,
                    b2 + l*CC, x, x, nullptr, nullptr,
                    MROWS, CC, CC, DFF, 0);
    }

    ln_kernel<<<MROWS, CC>>>(x, lnf_g, lnf_b, hh, hl);

    // logits = h @ lm_w + lm_b
    launch_gemm(hh, hl, lmh, lml, lm_b, nullptr, out, nullptr, nullptr,
                MROWS, VV, VPAD, CC, 0);
}

// round 10
// speedup vs baseline: 2.6862x; 1.3081x over previous
#include <cuda_runtime.h>
#include <cuda_bf16.h>
#include <math_constants.h>
#include <cstdint>

// Problem constants
#define BB 128
#define TT 128
#define CC 256
#define HH 4
#define LL 6
#define VV 10000
#define HS 64
#define DFF 1024
#define MROWS (BB*TT)   // 16384
#define VPAD 10112      // 79*128
#define NQKV 768

// ---------------------------------------------------------------------------
// Scratch (device globals; no allocation allowed)
// ---------------------------------------------------------------------------
__device__ float g_x  [MROWS*CC];        // residual stream (fp32)
__device__ float g_qkv[MROWS*NQKV];      // fused qkv output (fp32)
__device__ __nv_bfloat16 g_hh[MROWS*CC],  g_hl[MROWS*CC];    // LN out hi/lo
__device__ __nv_bfloat16 g_ath[MROWS*CC], g_atl[MROWS*CC];   // attn out hi/lo
__device__ __nv_bfloat16 g_ffh[MROWS*DFF], g_ffl[MROWS*DFF]; // MLP hidden hi/lo
// packed weights: bf16 hi/lo, [N,K] K-major
__device__ __nv_bfloat16 g_qkvh[LL*NQKV*CC], g_qkvl[LL*NQKV*CC];
__device__ __nv_bfloat16 g_pwh[LL*CC*CC],  g_pwl[LL*CC*CC];
__device__ __nv_bfloat16 g_w1h[LL*DFF*CC], g_w1l[LL*DFF*CC];
__device__ __nv_bfloat16 g_w2h[LL*CC*DFF], g_w2l[LL*CC*DFF];
__device__ __nv_bfloat16 g_lmh[VPAD*CC],   g_lml[VPAD*CC];

// ---------------------------------------------------------------------------
// PTX primitives (all valid on plain compute_103)
// ---------------------------------------------------------------------------
__device__ __forceinline__ void mma16816(float* d, const uint32_t* a, const uint32_t* b)
{
    asm volatile(
        "mma.sync.aligned.m16n8k16.row.col.f32.bf16.bf16.f32 "
        "{%0,%1,%2,%3}, {%4,%5,%6,%7}, {%8,%9}, {%0,%1,%2,%3};"
        : "+f"(d[0]), "+f"(d[1]), "+f"(d[2]), "+f"(d[3])
        : "r"(a[0]), "r"(a[1]), "r"(a[2]), "r"(a[3]), "r"(b[0]), "r"(b[1]));
}
__device__ __forceinline__ void ldsm_x4(uint32_t* r, uint32_t addr)
{
    asm volatile("ldmatrix.sync.aligned.m8n8.x4.shared.b16 {%0,%1,%2,%3}, [%4];"
        : "=r"(r[0]), "=r"(r[1]), "=r"(r[2]), "=r"(r[3]) : "r"(addr));
}
__device__ __forceinline__ uint32_t smem_u32(const void* p) {
    uint32_t a;
    asm("{ .reg .u64 t; cvta.to.shared.u64 t, %1; cvt.u32.u64 %0, t; }" : "=r"(a) : "l"(p));
    return a;
}
#define CP16(dst, src) \
    asm volatile("cp.async.cg.shared.global [%0], [%1], 16;" :: "r"(dst), "l"(src))
#define CP_COMMIT() asm volatile("cp.async.commit_group;" ::: "memory")
#define CP_WAIT(n)  asm volatile("cp.async.wait_group %0;" :: "n"(n) : "memory")

__device__ __forceinline__ void split_bf16(float v, __nv_bfloat16& h, __nv_bfloat16& l)
{
    h = __float2bfloat16(v);
    l = __float2bfloat16(v - __bfloat162float(h));
}
__device__ __forceinline__ uint32_t pack2(__nv_bfloat16 a, __nv_bfloat16 b)
{
    return ((uint32_t)__bfloat16_as_ushort(b) << 16) | __bfloat16_as_ushort(a);
}

// ---------------------------------------------------------------------------
// Weight prepack: W[L][K][N] fp32 -> Oh/Ol[L][NPAD][K] bf16 hi/lo, transposed.
// ---------------------------------------------------------------------------
__global__ void prep_kernel(const float* __restrict__ W,
                            __nv_bfloat16* __restrict__ Oh,
                            __nv_bfloat16* __restrict__ Ol,
                            int K, int N, size_t wstride, size_t ostride)
{
    __shared__ float t[32][33];
    W  += blockIdx.z * wstride;
    Oh += blockIdx.z * ostride;
    Ol += blockIdx.z * ostride;
    int nb = blockIdx.x * 32, kb = blockIdx.y * 32;
    int tx = threadIdx.x, ty = threadIdx.y;
    #pragma unroll
    for (int r = 0; r < 32; r += 8) {
        int k = kb + ty + r, n = nb + tx;
        t[ty + r][tx] = (n < N) ? W[(size_t)k * N + n] : 0.f;
    }
    __syncthreads();
    #pragma unroll
    for (int r = 0; r < 32; r += 8) {
        int n = nb + ty + r, k = kb + tx;
        float v = t[tx][ty + r];
        __nv_bfloat16 h, l;
        split_bf16(v, h, l);
        Oh[(size_t)n * K + k] = h;
        Ol[(size_t)n * K + k] = l;
    }
}

// ---------------------------------------------------------------------------
// Embedding
// ---------------------------------------------------------------------------
__global__ void embed_kernel(const int* __restrict__ idx,
                             const float* __restrict__ tok,
                             const float* __restrict__ pos,
                             float* __restrict__ x)
{
    int row = blockIdx.x;
    int tid = threadIdx.x;
    int token = idx[row];
    x[(size_t)row*CC + tid] = tok[(size_t)token*CC + tid] + pos[(row & (TT-1))*CC + tid];
}

// ---------------------------------------------------------------------------
// LayerNorm: warp per row (8 rows/block), single-pass sum/sumsq, no barriers.
// Output bf16 hi/lo split. grid = MROWS/8, block = 256.
// ---------------------------------------------------------------------------
__global__ __launch_bounds__(256) void ln_kernel(
    const float* __restrict__ x,
    const float* __restrict__ g,
    const float* __restrict__ b,
    __nv_bfloat16* __restrict__ oh,
    __nv_bfloat16* __restrict__ ol)
{
    int wid  = threadIdx.x >> 5;
    int lane = threadIdx.x & 31;
    int row  = blockIdx.x * 8 + wid;
    int c0   = lane * 8;

    const float* xr = x + (size_t)row*CC + c0;
    float4 v0 = *(const float4*)xr;
    float4 v1 = *(const float4*)(xr + 4);

    float sum = v0.x + v0.y + v0.z + v0.w + v1.x + v1.y + v1.z + v1.w;
    float sq  = v0.x*v0.x + v0.y*v0.y + v0.z*v0.z + v0.w*v0.w
              + v1.x*v1.x + v1.y*v1.y + v1.z*v1.z + v1.w*v1.w;
    #pragma unroll
    for (int o = 16; o; o >>= 1) {
        sum += __shfl_xor_sync(0xffffffffu, sum, o);
        sq  += __shfl_xor_sync(0xffffffffu, sq,  o);
    }
    float mean = sum * (1.f/CC);
    float var  = fmaxf(sq * (1.f/CC) - mean*mean, 0.f);
    float rs   = rsqrtf(var + 1e-5f);

    float4 g0 = *(const float4*)&g[c0];
    float4 g1 = *(const float4*)&g[c0 + 4];
    float4 b0 = *(const float4*)&b[c0];
    float4 b1 = *(const float4*)&b[c0 + 4];

    float y[8];
    y[0] = (v0.x - mean)*rs*g0.x + b0.x;
    y[1] = (v0.y - mean)*rs*g0.y + b0.y;
    y[2] = (v0.z - mean)*rs*g0.z + b0.z;
    y[3] = (v0.w - mean)*rs*g0.w + b0.w;
    y[4] = (v1.x - mean)*rs*g1.x + b1.x;
    y[5] = (v1.y - mean)*rs*g1.y + b1.y;
    y[6] = (v1.z - mean)*rs*g1.z + b1.z;
    y[7] = (v1.w - mean)*rs*g1.w + b1.w;

    uint4 ph, pl;
    __nv_bfloat16 hh, ll;
    uint32_t hw[8];
    #pragma unroll
    for (int i = 0; i < 8; i += 2) {
        __nv_bfloat16 h0, l0, h1, l1;
        split_bf16(y[i],   h0, l0);
        split_bf16(y[i+1], h1, l1);
        hw[i]   = pack2(h0, h1);
        hw[i+1] = pack2(l0, l1);
    }
    ph.x = hw[0]; ph.y = hw[2]; ph.z = hw[4]; ph.w = hw[6];
    pl.x = hw[1]; pl.y = hw[3]; pl.z = hw[5]; pl.w = hw[7];
    *(uint4*)&oh[(size_t)row*CC + c0] = ph;
    *(uint4*)&ol[(size_t)row*CC + c0] = pl;
    (void)hh; (void)ll;
}

// ---------------------------------------------------------------------------
// HMMA GEMM (bf16x3 split), 128x128x32 tile, 8 warps, ldmatrix + cp.async,
// 2 CTAs/SM target.
// ---------------------------------------------------------------------------
#define PITCH 40
#define TILE_B (128*PITCH*2)            // bytes per tile array (10240)
#define BUF_B  (4*TILE_B)               // Ah, Al, Bh, Bl (40960)
#define GEMM_SMEM (2*BUF_B)             // 81920

__device__ __forceinline__ void load_tiles_async(
    uint32_t sdst,
    const __nv_bfloat16* __restrict__ Ah, const __nv_bfloat16* __restrict__ Al,
    const __nv_bfloat16* __restrict__ Bh, const __nv_bfloat16* __restrict__ Bl,
    int row0, int col0, int kt, int K, int tid)
{
    #pragma unroll
    for (int half = 0; half < 2; half++) {
        int slot = tid + half*256;
        int r = slot >> 2, c8 = (slot & 3) << 3;
        uint32_t doff = (uint32_t)(r*PITCH + c8)*2;
        size_t ga = (size_t)(row0 + r)*K + kt + c8;
        size_t gb = (size_t)(col0 + r)*K + kt + c8;
        CP16(sdst + 0*TILE_B + doff, Ah + ga);
        CP16(sdst + 1*TILE_B + doff, Al + ga);
        CP16(sdst + 2*TILE_B + doff, Bh + gb);
        CP16(sdst + 3*TILE_B + doff, Bl + gb);
    }
}

__global__ __launch_bounds__(256, 2) void gemm_mma(
    const __nv_bfloat16* __restrict__ Ah, const __nv_bfloat16* __restrict__ Al,
    const __nv_bfloat16* __restrict__ Bh, const __nv_bfloat16* __restrict__ Bl,
    const float* __restrict__ bias, const float* __restrict__ resid,
    float* __restrict__ C,
    __nv_bfloat16* __restrict__ Ch, __nv_bfloat16* __restrict__ Cl,
    int M, int N, int K, int relu)
{
    extern __shared__ char smem[];
    uint32_t s0 = smem_u32(smem);

    int tid  = threadIdx.x;
    int lane = tid & 31;
    int wid  = tid >> 5;
    int wm   = wid & 1;
    int wn   = wid >> 1;
    int g    = lane >> 2;
    int tg   = lane & 3;
    int row0 = blockIdx.y * 128;
    int col0 = blockIdx.x * 128;

    uint32_t a_lane = (uint32_t)((wm*64 + (lane & 7) + ((lane >> 3) & 1)*8)*PITCH
                                 + (lane >> 4)*8) * 2;
    uint32_t b_lane = (uint32_t)((wn*32 + (lane & 7) + ((lane >> 4) & 1)*8)*PITCH
                                 + ((lane >> 3) & 1)*8) * 2;

    float acc[4][4][4];
    #pragma unroll
    for (int mi = 0; mi < 4; mi++)
        #pragma unroll
        for (int ni = 0; ni < 4; ni++)
            #pragma unroll
            for (int e = 0; e < 4; e++) acc[mi][ni][e] = 0.f;

    int nkb = K >> 5;
    load_tiles_async(s0, Ah, Al, Bh, Bl, row0, col0, 0, K, tid);
    CP_COMMIT();

    for (int kb = 0; kb < nkb; kb++) {
        if (kb + 1 < nkb) {
            load_tiles_async(s0 + ((kb + 1) & 1)*BUF_B, Ah, Al, Bh, Bl,
                             row0, col0, (kb + 1) << 5, K, tid);
            CP_COMMIT();
            CP_WAIT(1);
        } else {
            CP_WAIT(0);
        }
        __syncthreads();

        uint32_t bufb = s0 + (kb & 1)*BUF_B;
        #pragma unroll
        for (int ks = 0; ks < 2; ks++) {
            uint32_t tb[4];
            uint32_t fbh[4][2], fbl[4][2];
            ldsm_x4(tb, bufb + 2*TILE_B + b_lane + ks*32);
            fbh[0][0]=tb[0]; fbh[0][1]=tb[1]; fbh[1][0]=tb[2]; fbh[1][1]=tb[3];
            ldsm_x4(tb, bufb + 2*TILE_B + b_lane + 16*PITCH*2 + ks*32);
            fbh[2][0]=tb[0]; fbh[2][1]=tb[1]; fbh[3][0]=tb[2]; fbh[3][1]=tb[3];
            ldsm_x4(tb, bufb + 3*TILE_B + b_lane + ks*32);
            fbl[0][0]=tb[0]; fbl[0][1]=tb[1]; fbl[1][0]=tb[2]; fbl[1][1]=tb[3];
            ldsm_x4(tb, bufb + 3*TILE_B + b_lane + 16*PITCH*2 + ks*32);
            fbl[2][0]=tb[0]; fbl[2][1]=tb[1]; fbl[3][0]=tb[2]; fbl[3][1]=tb[3];

            #pragma unroll
            for (int mi = 0; mi < 4; mi++) {
                uint32_t fah[4], fal[4];
                uint32_t ao = a_lane + (uint32_t)(mi*16*PITCH*2) + ks*32;
                ldsm_x4(fah, bufb + 0*TILE_B + ao);
                ldsm_x4(fal, bufb + 1*TILE_B + ao);
                #pragma unroll
                for (int ni = 0; ni < 4; ni++) {
                    mma16816(acc[mi][ni], fah, fbh[ni]);
                    mma16816(acc[mi][ni], fah, fbl[ni]);
                    mma16816(acc[mi][ni], fal, fbh[ni]);
                }
            }
        }
        __syncthreads();
    }

    // Epilogue
    #pragma unroll
    for (int mi = 0; mi < 4; mi++) {
        #pragma unroll
        for (int r2 = 0; r2 < 2; r2++) {
            int grow = row0 + wm*64 + mi*16 + g + r2*8;
            #pragma unroll
            for (int ni = 0; ni < 4; ni++) {
                int c = col0 + wn*32 + ni*8 + tg*2;
                float v0 = acc[mi][ni][r2*2];
                float v1 = acc[mi][ni][r2*2 + 1];
                if (bias)  { v0 += bias[c]; v1 += bias[c+1]; }
                if (relu)  { v0 = fmaxf(v0, 0.f); v1 = fmaxf(v1, 0.f); }
                if (C) {
                    if (c < N) {
                        if (resid) {
                            float2 rr = *(const float2*)&resid[(size_t)grow*N + c];
                            v0 += rr.x; v1 += rr.y;
                        }
                        float2 o; o.x = v0; o.y = v1;
                        *(float2*)&C[(size_t)grow*N + c] = o;
                    }
                } else {
                    __nv_bfloat16 h0, l0, h1, l1;
                    split_bf16(v0, h0, l0);
                    split_bf16(v1, h1, l1);
                    *(uint32_t*)&Ch[(size_t)grow*N + c] = pack2(h0, h1);
                    *(uint32_t*)&Cl[(size_t)grow*N + c] = pack2(l0, l1);
                }
            }
        }
    }
}

// ---------------------------------------------------------------------------
// Attention: block per (b,h), thread = query row, online softmax.
// Score dot-product split into 4 independent partial chains for ILP.
// ---------------------------------------------------------------------------
__global__ __launch_bounds__(128) void attn_kernel(
    const float* __restrict__ QKV,
    __nv_bfloat16* __restrict__ Oh, __nv_bfloat16* __restrict__ Ol)
{
    __shared__ float ks[64][64];
    __shared__ float vs[64][64];

    int bh = blockIdx.x;
    int b  = bh >> 2;
    int h  = bh & 3;
    int t  = threadIdx.x;
    const float scale = 0.0625f;

    const float* qp = QKV + ((size_t)b*TT + t)*NQKV + h*HS;
    float q[HS];
    #pragma unroll
    for (int d = 0; d < HS; d++) q[d] = qp[d] * scale;

    float m = -CUDART_INF_F;
    float s = 0.f;
    float acc[HS];
    #pragma unroll
    for (int d = 0; d < HS; d++) acc[d] = 0.f;

    for (int kc = 0; kc < TT; kc += 64) {
        __syncthreads();
        for (int i = t; i < 64*16; i += 128) {
            int r = i >> 4;
            int c = (i & 15) * 4;
            size_t go = ((size_t)b*TT + kc + r)*NQKV + h*HS + c;
            *(float4*)&ks[r][c] = *(const float4*)&QKV[go + 256];
            *(float4*)&vs[r][c] = *(const float4*)&QKV[go + 512];
        }
        __syncthreads();

        int jmax = t - kc + 1;
        if (jmax > 64) jmax = 64;
        for (int j = 0; j < jmax; j++) {
            const float* kj = ks[j];
            float s0 = 0.f, s1 = 0.f, s2 = 0.f, s3 = 0.f;
            #pragma unroll
            for (int d = 0; d < HS; d += 4) {
                s0 += q[d]   * kj[d];
                s1 += q[d+1] * kj[d+1];
                s2 += q[d+2] * kj[d+2];
                s3 += q[d+3] * kj[d+3];
            }
            float sc = (s0 + s1) + (s2 + s3);
            float nm = fmaxf(m, sc);
            float f  = __expf(m  - nm);
            float e  = __expf(sc - nm);
            s = s * f + e;
            const float* vj = vs[j];
            #pragma unroll
            for (int d = 0; d < HS; d++) acc[d] = acc[d] * f + e * vj[d];
            m = nm;
        }
    }

    float inv = 1.f / s;
    size_t oo = ((size_t)b*TT + t)*CC + h*HS;
    #pragma unroll
    for (int d = 0; d < HS; d += 2) {
        __nv_bfloat16 h0, l0, h1, l1;
        split_bf16(acc[d]   * inv, h0, l0);
        split_bf16(acc[d+1] * inv, h1, l1);
        *(uint32_t*)&Oh[oo + d] = pack2(h0, h1);
        *(uint32_t*)&Ol[oo + d] = pack2(l0, l1);
    }
}

// ---------------------------------------------------------------------------
// Launch helpers
// ---------------------------------------------------------------------------
static inline void launch_gemm(const __nv_bfloat16* Ah, const __nv_bfloat16* Al,
                               const __nv_bfloat16* Bh, const __nv_bfloat16* Bl,
                               const float* bias, const float* resid,
                               float* C, __nv_bfloat16* Ch, __nv_bfloat16* Cl,
                               int M, int N, int NPAD, int K, int relu)
{
    dim3 grid(NPAD / 128, M / 128);
    gemm_mma<<<grid, 256, GEMM_SMEM>>>(Ah, Al, Bh, Bl, bias, resid, C, Ch, Cl,
                                       M, N, K, relu);
}

extern "C" void kernel_launch(void* const* d_in, const int* in_sizes, int n_in,
                              void* d_out, int out_size)
{
    const int*   idx     = (const int*)  d_in[0];
    const float* tok_emb = (const float*)d_in[1];
    const float* pos_emb = (const float*)d_in[2];
    const float* ln1_g   = (const float*)d_in[3];
    const float* ln1_b   = (const float*)d_in[4];
    const float* wq      = (const float*)d_in[5];
    const float* wk      = (const float*)d_in[6];
    const float* wv      = (const float*)d_in[7];
    const float* proj_w  = (const float*)d_in[8];
    const float* proj_b  = (const float*)d_in[9];
    const float* ln2_g   = (const float*)d_in[10];
    const float* ln2_b   = (const float*)d_in[11];
    const float* w1      = (const float*)d_in[12];
    const float* b1      = (const float*)d_in[13];
    const float* w2      = (const float*)d_in[14];
    const float* b2      = (const float*)d_in[15];
    const float* lnf_g   = (const float*)d_in[16];
    const float* lnf_b   = (const float*)d_in[17];
    const float* lm_w    = (const float*)d_in[18];
    const float* lm_b    = (const float*)d_in[19];
    float* out = (float*)d_out;

    cudaFuncSetAttribute(gemm_mma, cudaFuncAttributeMaxDynamicSharedMemorySize, GEMM_SMEM);

    float *x, *qkv;
    cudaGetSymbolAddress((void**)&x,   g_x);
    cudaGetSymbolAddress((void**)&qkv, g_qkv);
    __nv_bfloat16 *hh,*hl,*ath,*atl,*ffh,*ffl;
    cudaGetSymbolAddress((void**)&hh,  g_hh);  cudaGetSymbolAddress((void**)&hl,  g_hl);
    cudaGetSymbolAddress((void**)&ath, g_ath); cudaGetSymbolAddress((void**)&atl, g_atl);
    cudaGetSymbolAddress((void**)&ffh, g_ffh); cudaGetSymbolAddress((void**)&ffl, g_ffl);
    __nv_bfloat16 *qkvh,*qkvl,*pwh,*pwl,*w1h,*w1l,*w2h,*w2l,*lmh,*lml;
    cudaGetSymbolAddress((void**)&qkvh, g_qkvh); cudaGetSymbolAddress((void**)&qkvl, g_qkvl);
    cudaGetSymbolAddress((void**)&pwh,  g_pwh);  cudaGetSymbolAddress((void**)&pwl,  g_pwl);
    cudaGetSymbolAddress((void**)&w1h,  g_w1h);  cudaGetSymbolAddress((void**)&w1l,  g_w1l);
    cudaGetSymbolAddress((void**)&w2h,  g_w2h);  cudaGetSymbolAddress((void**)&w2l,  g_w2l);
    cudaGetSymbolAddress((void**)&lmh,  g_lmh);  cudaGetSymbolAddress((void**)&lml,  g_lml);

    // ---- prepack weights (batched over layers via gridDim.z) ----
    dim3 pb(32, 8);
    prep_kernel<<<dim3(CC/32, CC/32, LL),  pb>>>(wq,     qkvh + 0*CC*CC, qkvl + 0*CC*CC, CC, CC, (size_t)CC*CC, (size_t)NQKV*CC);
    prep_kernel<<<dim3(CC/32, CC/32, LL),  pb>>>(wk,     qkvh + 1*CC*CC, qkvl + 1*CC*CC, CC, CC, (size_t)CC*CC, (size_t)NQKV*CC);
    prep_kernel<<<dim3(CC/32, CC/32, LL),  pb>>>(wv,     qkvh + 2*CC*CC, qkvl + 2*CC*CC, CC, CC, (size_t)CC*CC, (size_t)NQKV*CC);
    prep_kernel<<<dim3(CC/32, CC/32, LL),  pb>>>(proj_w, pwh, pwl, CC, CC,  (size_t)CC*CC,  (size_t)CC*CC);
    prep_kernel<<<dim3(DFF/32, CC/32, LL), pb>>>(w1,     w1h, w1l, CC, DFF, (size_t)CC*DFF, (size_t)DFF*CC);
    prep_kernel<<<dim3(CC/32, DFF/32, LL), pb>>>(w2,     w2h, w2l, DFF, CC, (size_t)DFF*CC, (size_t)CC*DFF);
    prep_kernel<<<dim3(VPAD/32, CC/32, 1), pb>>>(lm_w,   lmh, lml, CC, VV, 0, 0);

    // ---- forward ----
    embed_kernel<<<MROWS, CC>>>(idx, tok_emb, pos_emb, x);

    for (int l = 0; l < LL; l++) {
        ln_kernel<<<MROWS/8, 256>>>(x, ln1_g + l*CC, ln1_b + l*CC, hh, hl);

        launch_gemm(hh, hl, qkvh + (size_t)l*NQKV*CC, qkvl + (size_t)l*NQKV*CC,
                    nullptr, nullptr, qkv, nullptr, nullptr,
                    MROWS, NQKV, NQKV, CC, 0);

        attn_kernel<<<BB*HH, TT>>>(qkv, ath, atl);

        launch_gemm(ath, atl, pwh + (size_t)l*CC*CC, pwl + (size_t)l*CC*CC,
                    proj_b + l*CC, x, x, nullptr, nullptr,
                    MROWS, CC, CC, CC, 0);

        ln_kernel<<<MROWS/8, 256>>>(x, ln2_g + l*CC, ln2_b + l*CC, hh, hl);

        launch_gemm(hh, hl, w1h + (size_t)l*DFF*CC, w1l + (size_t)l*DFF*CC,
                    b1 + l*DFF, nullptr, nullptr, ffh, ffl,
                    MROWS, DFF, DFF, CC, 1);

        launch_gemm(ffh, ffl, w2h + (size_t)l*CC*DFF, w2l + (size_t)l*CC*DFF,
                    b2 + l*CC, x, x, nullptr, nullptr,
                    MROWS, CC, CC, DFF, 0);
    }

    ln_kernel<<<MROWS/8, 256>>>(x, lnf_g, lnf_b, hh, hl);

    launch_gemm(hh, hl, lmh, lml, lm_b, nullptr, out, nullptr, nullptr,
                MROWS, VV, VPAD, CC, 0);
}

// round 13
// speedup vs baseline: 2.7394x; 1.0198x over previous
#include <cuda_runtime.h>
#include <cuda_bf16.h>
#include <math_constants.h>
#include <cstdint>

// Problem constants
#define BB 128
#define TT 128
#define CC 256
#define HH 4
#define LL 6
#define VV 10000
#define HS 64
#define DFF 1024
#define MROWS (BB*TT)   // 16384
#define VPAD 10112      // 79*128
#define NQKV 768

// ---------------------------------------------------------------------------
// Scratch (device globals; no allocation allowed)
// ---------------------------------------------------------------------------
__device__ float g_x  [MROWS*CC];
__device__ float g_qkv[MROWS*NQKV];
__device__ __nv_bfloat16 g_hh[MROWS*CC],  g_hl[MROWS*CC];
__device__ __nv_bfloat16 g_ath[MROWS*CC], g_atl[MROWS*CC];
__device__ __nv_bfloat16 g_ffh[MROWS*DFF], g_ffl[MROWS*DFF];
__device__ __nv_bfloat16 g_qkvh[LL*NQKV*CC], g_qkvl[LL*NQKV*CC];
__device__ __nv_bfloat16 g_pwh[LL*CC*CC],  g_pwl[LL*CC*CC];
__device__ __nv_bfloat16 g_w1h[LL*DFF*CC], g_w1l[LL*DFF*CC];
__device__ __nv_bfloat16 g_w2h[LL*CC*DFF], g_w2l[LL*CC*DFF];
__device__ __nv_bfloat16 g_lmh[VPAD*CC],   g_lml[VPAD*CC];

// ---------------------------------------------------------------------------
// PTX primitives
// ---------------------------------------------------------------------------
__device__ __forceinline__ void mma16816(float* d, const uint32_t* a, const uint32_t* b)
{
    asm volatile(
        "mma.sync.aligned.m16n8k16.row.col.f32.bf16.bf16.f32 "
        "{%0,%1,%2,%3}, {%4,%5,%6,%7}, {%8,%9}, {%0,%1,%2,%3};"
        : "+f"(d[0]), "+f"(d[1]), "+f"(d[2]), "+f"(d[3])
        : "r"(a[0]), "r"(a[1]), "r"(a[2]), "r"(a[3]), "r"(b[0]), "r"(b[1]));
}
__device__ __forceinline__ void ldsm_x4(uint32_t* r, uint32_t addr)
{
    asm volatile("ldmatrix.sync.aligned.m8n8.x4.shared.b16 {%0,%1,%2,%3}, [%4];"
        : "=r"(r[0]), "=r"(r[1]), "=r"(r[2]), "=r"(r[3]) : "r"(addr));
}
__device__ __forceinline__ uint32_t smem_u32(const void* p) {
    uint32_t a;
    asm("{ .reg .u64 t; cvta.to.shared.u64 t, %1; cvt.u32.u64 %0, t; }" : "=r"(a) : "l"(p));
    return a;
}
#define CP16(dst, src) \
    asm volatile("cp.async.cg.shared.global [%0], [%1], 16;" :: "r"(dst), "l"(src))
#define CP_COMMIT() asm volatile("cp.async.commit_group;" ::: "memory")
#define CP_WAIT(n)  asm volatile("cp.async.wait_group %0;" :: "n"(n) : "memory")

__device__ __forceinline__ void split_bf16(float v, __nv_bfloat16& h, __nv_bfloat16& l)
{
    h = __float2bfloat16(v);
    l = __float2bfloat16(v - __bfloat162float(h));
}
__device__ __forceinline__ uint32_t pack2(__nv_bfloat16 a, __nv_bfloat16 b)
{
    return ((uint32_t)__bfloat16_as_ushort(b) << 16) | __bfloat16_as_ushort(a);
}

// ---------------------------------------------------------------------------
// Mega weight prepack: one launch, compile-time segment table.
// Each block = one 32x32 transpose tile. Grid.x = 7136.
//   [0,1152)    wq/wk/wv  (3 kinds x 6 layers x 64 tiles)  K=256,N=256
//   [1152,1536) proj      (6 x 64)                          K=256,N=256
//   [1536,3072) w1        (6 x 256)                         K=256,N=1024
//   [3072,4608) w2        (6 x 256)                         K=1024,N=256
//   [4608,7136) lm        (316 nb x 8 kb)                   K=256,N=10000->VPAD
// ---------------------------------------------------------------------------
__global__ void prep_all(
    const float* __restrict__ wq, const float* __restrict__ wk,
    const float* __restrict__ wv, const float* __restrict__ proj,
    const float* __restrict__ w1, const float* __restrict__ w2,
    const float* __restrict__ lm,
    __nv_bfloat16* __restrict__ qkvh, __nv_bfloat16* __restrict__ qkvl,
    __nv_bfloat16* __restrict__ pwh,  __nv_bfloat16* __restrict__ pwl,
    __nv_bfloat16* __restrict__ w1h,  __nv_bfloat16* __restrict__ w1l,
    __nv_bfloat16* __restrict__ w2h,  __nv_bfloat16* __restrict__ w2l,
    __nv_bfloat16* __restrict__ lmh,  __nv_bfloat16* __restrict__ lml)
{
    int t = blockIdx.x;
    const float* W;
    __nv_bfloat16 *Oh, *Ol;
    int K, N, nb, kb;

    if (t < 1152) {
        int kind  = t / 384, rem = t % 384;
        int layer = rem / 64, tt = rem % 64;
        const float* base = kind == 0 ? wq : (kind == 1 ? wk : wv);
        W  = base + (size_t)layer*CC*CC;
        Oh = qkvh + (size_t)layer*NQKV*CC + (size_t)kind*CC*CC;
        Ol = qkvl + (size_t)layer*NQKV*CC + (size_t)kind*CC*CC;
        K = CC; N = CC; nb = tt % 8; kb = tt / 8;
    } else if (t < 1536) {
        int rem = t - 1152, layer = rem / 64, tt = rem % 64;
        W  = proj + (size_t)layer*CC*CC;
        Oh = pwh + (size_t)layer*CC*CC;
        Ol = pwl + (size_t)layer*CC*CC;
        K = CC; N = CC; nb = tt % 8; kb = tt / 8;
    } else if (t < 3072) {
        int rem = t - 1536, layer = rem / 256, tt = rem % 256;
        W  = w1 + (size_t)layer*CC*DFF;
        Oh = w1h + (size_t)layer*DFF*CC;
        Ol = w1l + (size_t)layer*DFF*CC;
        K = CC; N = DFF; nb = tt % 32; kb = tt / 32;
    } else if (t < 4608) {
        int rem = t - 3072, layer = rem / 256, tt = rem % 256;
        W  = w2 + (size_t)layer*DFF*CC;
        Oh = w2h + (size_t)layer*CC*DFF;
        Ol = w2l + (size_t)layer*CC*DFF;
        K = DFF; N = CC; nb = tt % 8; kb = tt / 8;
    } else {
        int rem = t - 4608;
        W = lm; Oh = lmh; Ol = lml;
        K = CC; N = VV; nb = rem % 316; kb = rem / 316;
    }

    __shared__ float tbuf[32][33];
    int n0 = nb * 32, k0 = kb * 32;
    int tx = threadIdx.x, ty = threadIdx.y;
    #pragma unroll
    for (int r = 0; r < 32; r += 8) {
        int k = k0 + ty + r, n = n0 + tx;
        tbuf[ty + r][tx] = (n < N) ? W[(size_t)k * N + n] : 0.f;
    }
    __syncthreads();
    #pragma unroll
    for (int r = 0; r < 32; r += 8) {
        int n = n0 + ty + r, k = k0 + tx;
        float v = tbuf[tx][ty + r];
        __nv_bfloat16 h, l;
        split_bf16(v, h, l);
        Oh[(size_t)n * K + k] = h;
        Ol[(size_t)n * K + k] = l;
    }
}

// ---------------------------------------------------------------------------
// Embedding
// ---------------------------------------------------------------------------
__global__ void embed_kernel(const int* __restrict__ idx,
                             const float* __restrict__ tok,
                             const float* __restrict__ pos,
                             float* __restrict__ x)
{
    int row = blockIdx.x;
    int tid = threadIdx.x;
    int token = idx[row];
    x[(size_t)row*CC + tid] = tok[(size_t)token*CC + tid] + pos[(row & (TT-1))*CC + tid];
}

// ---------------------------------------------------------------------------
// LayerNorm: warp per row, single pass, bf16 hi/lo output.
// ---------------------------------------------------------------------------
__global__ __launch_bounds__(256) void ln_kernel(
    const float* __restrict__ x,
    const float* __restrict__ g,
    const float* __restrict__ b,
    __nv_bfloat16* __restrict__ oh,
    __nv_bfloat16* __restrict__ ol)
{
    int wid  = threadIdx.x >> 5;
    int lane = threadIdx.x & 31;
    int row  = blockIdx.x * 8 + wid;
    int c0   = lane * 8;

    const float* xr = x + (size_t)row*CC + c0;
    float4 v0 = *(const float4*)xr;
    float4 v1 = *(const float4*)(xr + 4);

    float sum = v0.x + v0.y + v0.z + v0.w + v1.x + v1.y + v1.z + v1.w;
    float sq  = v0.x*v0.x + v0.y*v0.y + v0.z*v0.z + v0.w*v0.w
              + v1.x*v1.x + v1.y*v1.y + v1.z*v1.z + v1.w*v1.w;
    #pragma unroll
    for (int o = 16; o; o >>= 1) {
        sum += __shfl_xor_sync(0xffffffffu, sum, o);
        sq  += __shfl_xor_sync(0xffffffffu, sq,  o);
    }
    float mean = sum * (1.f/CC);
    float var  = fmaxf(sq * (1.f/CC) - mean*mean, 0.f);
    float rs   = rsqrtf(var + 1e-5f);

    float4 g0 = *(const float4*)&g[c0];
    float4 g1 = *(const float4*)&g[c0 + 4];
    float4 b0 = *(const float4*)&b[c0];
    float4 b1 = *(const float4*)&b[c0 + 4];

    float y[8];
    y[0] = (v0.x - mean)*rs*g0.x + b0.x;
    y[1] = (v0.y - mean)*rs*g0.y + b0.y;
    y[2] = (v0.z - mean)*rs*g0.z + b0.z;
    y[3] = (v0.w - mean)*rs*g0.w + b0.w;
    y[4] = (v1.x - mean)*rs*g1.x + b1.x;
    y[5] = (v1.y - mean)*rs*g1.y + b1.y;
    y[6] = (v1.z - mean)*rs*g1.z + b1.z;
    y[7] = (v1.w - mean)*rs*g1.w + b1.w;

    uint4 ph, pl;
    uint32_t hw[8];
    #pragma unroll
    for (int i = 0; i < 8; i += 2) {
        __nv_bfloat16 h0, l0, h1, l1;
        split_bf16(y[i],   h0, l0);
        split_bf16(y[i+1], h1, l1);
        hw[i]   = pack2(h0, h1);
        hw[i+1] = pack2(l0, l1);
    }
    ph.x = hw[0]; ph.y = hw[2]; ph.z = hw[4]; ph.w = hw[6];
    pl.x = hw[1]; pl.y = hw[3]; pl.z = hw[5]; pl.w = hw[7];
    *(uint4*)&oh[(size_t)row*CC + c0] = ph;
    *(uint4*)&ol[(size_t)row*CC + c0] = pl;
}

// ---------------------------------------------------------------------------
// HMMA GEMM (bf16x3 split): 128x128x32 block tile, 4 warps, warp tile 64x64.
// 16 LDSM per 96 MMA per ks-step (-33% smem traffic vs 64x32 warps).
// 2 CTAs/SM. cp.async double buffer.
// ---------------------------------------------------------------------------
#define PITCH 40
#define TILE_B (128*PITCH*2)            // 10240 bytes per array
#define BUF_B  (4*TILE_B)               // Ah, Al, Bh, Bl
#define GEMM_SMEM (2*BUF_B)             // 81920

__device__ __forceinline__ void load_tiles_async(
    uint32_t sdst,
    const __nv_bfloat16* __restrict__ Ah, const __nv_bfloat16* __restrict__ Al,
    const __nv_bfloat16* __restrict__ Bh, const __nv_bfloat16* __restrict__ Bl,
    int row0, int col0, int kt, int K, int tid)
{
    #pragma unroll
    for (int it = 0; it < 4; it++) {
        int slot = tid + it*128;            // 0..511 float4 slots per array
        int r = slot >> 2, c8 = (slot & 3) << 3;
        uint32_t doff = (uint32_t)(r*PITCH + c8)*2;
        size_t ga = (size_t)(row0 + r)*K + kt + c8;
        size_t gb = (size_t)(col0 + r)*K + kt + c8;
        CP16(sdst + 0*TILE_B + doff, Ah + ga);
        CP16(sdst + 1*TILE_B + doff, Al + ga);
        CP16(sdst + 2*TILE_B + doff, Bh + gb);
        CP16(sdst + 3*TILE_B + doff, Bl + gb);
    }
}

__global__ __launch_bounds__(128, 2) void gemm_mma(
    const __nv_bfloat16* __restrict__ Ah, const __nv_bfloat16* __restrict__ Al,
    const __nv_bfloat16* __restrict__ Bh, const __nv_bfloat16* __restrict__ Bl,
    const float* __restrict__ bias, const float* __restrict__ resid,
    float* __restrict__ C,
    __nv_bfloat16* __restrict__ Ch, __nv_bfloat16* __restrict__ Cl,
    int M, int N, int K, int relu)
{
    extern __shared__ char smem[];
    uint32_t s0 = smem_u32(smem);

    int tid  = threadIdx.x;
    int lane = tid & 31;
    int wid  = tid >> 5;       // 4 warps: 2M x 2N
    int wm   = wid & 1;
    int wn   = wid >> 1;
    int g    = lane >> 2;
    int tg   = lane & 3;
    int row0 = blockIdx.y * 128;
    int col0 = blockIdx.x * 128;

    // per-lane ldmatrix offsets (bytes) for a 16x16 region
    uint32_t a_lane = (uint32_t)((wm*64 + (lane & 7) + ((lane >> 3) & 1)*8)*PITCH
                                 + (lane >> 4)*8) * 2;
    uint32_t b_lane = (uint32_t)((wn*64 + (lane & 7) + ((lane >> 4) & 1)*8)*PITCH
                                 + ((lane >> 3) & 1)*8) * 2;

    float acc[4][8][4];
    #pragma unroll
    for (int mi = 0; mi < 4; mi++)
        #pragma unroll
        for (int ni = 0; ni < 8; ni++)
            #pragma unroll
            for (int e = 0; e < 4; e++) acc[mi][ni][e] = 0.f;

    int nkb = K >> 5;
    load_tiles_async(s0, Ah, Al, Bh, Bl, row0, col0, 0, K, tid);
    CP_COMMIT();

    for (int kb = 0; kb < nkb; kb++) {
        if (kb + 1 < nkb) {
            load_tiles_async(s0 + ((kb + 1) & 1)*BUF_B, Ah, Al, Bh, Bl,
                             row0, col0, (kb + 1) << 5, K, tid);
            CP_COMMIT();
            CP_WAIT(1);
        } else {
            CP_WAIT(0);
        }
        __syncthreads();

        uint32_t bufb = s0 + (kb & 1)*BUF_B;
        #pragma unroll
        for (int ks = 0; ks < 2; ks++) {
            // B fragments: 4 regions of 16 rows -> 8 n8-frags, hi + lo
            uint32_t fbh[8][2], fbl[8][2];
            #pragma unroll
            for (int r4 = 0; r4 < 4; r4++) {
                uint32_t tb[4];
                uint32_t off = b_lane + (uint32_t)(r4*16*PITCH*2) + ks*32;
                ldsm_x4(tb, bufb + 2*TILE_B + off);
                fbh[r4*2][0]=tb[0]; fbh[r4*2][1]=tb[1];
                fbh[r4*2+1][0]=tb[2]; fbh[r4*2+1][1]=tb[3];
                ldsm_x4(tb, bufb + 3*TILE_B + off);
                fbl[r4*2][0]=tb[0]; fbl[r4*2][1]=tb[1];
                fbl[r4*2+1][0]=tb[2]; fbl[r4*2+1][1]=tb[3];
            }
            #pragma unroll
            for (int mi = 0; mi < 4; mi++) {
                uint32_t fah[4], fal[4];
                uint32_t ao = a_lane + (uint32_t)(mi*16*PITCH*2) + ks*32;
                ldsm_x4(fah, bufb + 0*TILE_B + ao);
                ldsm_x4(fal, bufb + 1*TILE_B + ao);
                #pragma unroll
                for (int ni = 0; ni < 8; ni++) {
                    mma16816(acc[mi][ni], fah, fbh[ni]);
                    mma16816(acc[mi][ni], fah, fbl[ni]);
                    mma16816(acc[mi][ni], fal, fbh[ni]);
                }
            }
        }
        __syncthreads();
    }

    // Epilogue
    #pragma unroll
    for (int mi = 0; mi < 4; mi++) {
        #pragma unroll
        for (int r2 = 0; r2 < 2; r2++) {
            int grow = row0 + wm*64 + mi*16 + g + r2*8;
            #pragma unroll
            for (int ni = 0; ni < 8; ni++) {
                int c = col0 + wn*64 + ni*8 + tg*2;
                float v0 = acc[mi][ni][r2*2];
                float v1 = acc[mi][ni][r2*2 + 1];
                if (bias)  { v0 += bias[c]; v1 += bias[c+1]; }
                if (relu)  { v0 = fmaxf(v0, 0.f); v1 = fmaxf(v1, 0.f); }
                if (C) {
                    if (c < N) {
                        if (resid) {
                            float2 rr = *(const float2*)&resid[(size_t)grow*N + c];
                            v0 += rr.x; v1 += rr.y;
                        }
                        float2 o; o.x = v0; o.y = v1;
                        *(float2*)&C[(size_t)grow*N + c] = o;
                    }
                } else {
                    __nv_bfloat16 h0, l0, h1, l1;
                    split_bf16(v0, h0, l0);
                    split_bf16(v1, h1, l1);
                    *(uint32_t*)&Ch[(size_t)grow*N + c] = pack2(h0, h1);
                    *(uint32_t*)&Cl[(size_t)grow*N + c] = pack2(l0, l1);
                }
            }
        }
    }
}

// ---------------------------------------------------------------------------
// Attention: block per (b,h), thread = query row, online softmax.
// ---------------------------------------------------------------------------
__global__ __launch_bounds__(128) void attn_kernel(
    const float* __restrict__ QKV,
    __nv_bfloat16* __restrict__ Oh, __nv_bfloat16* __restrict__ Ol)
{
    __shared__ float ks[64][64];
    __shared__ float vs[64][64];

    int bh = blockIdx.x;
    int b  = bh >> 2;
    int h  = bh & 3;
    int t  = threadIdx.x;
    const float scale = 0.0625f;

    const float* qp = QKV + ((size_t)b*TT + t)*NQKV + h*HS;
    float q[HS];
    #pragma unroll
    for (int d = 0; d < HS; d++) q[d] = qp[d] * scale;

    float m = -CUDART_INF_F;
    float s = 0.f;
    float acc[HS];
    #pragma unroll
    for (int d = 0; d < HS; d++) acc[d] = 0.f;

    for (int kc = 0; kc < TT; kc += 64) {
        __syncthreads();
        for (int i = t; i < 64*16; i += 128) {
            int r = i >> 4;
            int c = (i & 15) * 4;
            size_t go = ((size_t)b*TT + kc + r)*NQKV + h*HS + c;
            *(float4*)&ks[r][c] = *(const float4*)&QKV[go + 256];
            *(float4*)&vs[r][c] = *(const float4*)&QKV[go + 512];
        }
        __syncthreads();

        int jmax = t - kc + 1;
        if (jmax > 64) jmax = 64;
        for (int j = 0; j < jmax; j++) {
            const float* kj = ks[j];
            float s0 = 0.f, s1 = 0.f, s2 = 0.f, s3 = 0.f;
            #pragma unroll
            for (int d = 0; d < HS; d += 4) {
                s0 += q[d]   * kj[d];
                s1 += q[d+1] * kj[d+1];
                s2 += q[d+2] * kj[d+2];
                s3 += q[d+3] * kj[d+3];
            }
            float sc = (s0 + s1) + (s2 + s3);
            float nm = fmaxf(m, sc);
            float f  = __expf(m  - nm);
            float e  = __expf(sc - nm);
            s = s * f + e;
            const float* vj = vs[j];
            #pragma unroll
            for (int d = 0; d < HS; d++) acc[d] = acc[d] * f + e * vj[d];
            m = nm;
        }
    }

    float inv = 1.f / s;
    size_t oo = ((size_t)b*TT + t)*CC + h*HS;
    #pragma unroll
    for (int d = 0; d < HS; d += 2) {
        __nv_bfloat16 h0, l0, h1, l1;
        split_bf16(acc[d]   * inv, h0, l0);
        split_bf16(acc[d+1] * inv, h1, l1);
        *(uint32_t*)&Oh[oo + d] = pack2(h0, h1);
        *(uint32_t*)&Ol[oo + d] = pack2(l0, l1);
    }
}

// ---------------------------------------------------------------------------
// Launch helpers
// ---------------------------------------------------------------------------
static inline void launch_gemm(const __nv_bfloat16* Ah, const __nv_bfloat16* Al,
                               const __nv_bfloat16* Bh, const __nv_bfloat16* Bl,
                               const float* bias, const float* resid,
                               float* C, __nv_bfloat16* Ch, __nv_bfloat16* Cl,
                               int M, int N, int NPAD, int K, int relu)
{
    dim3 grid(NPAD / 128, M / 128);
    gemm_mma<<<grid, 128, GEMM_SMEM>>>(Ah, Al, Bh, Bl, bias, resid, C, Ch, Cl,
                                       M, N, K, relu);
}

extern "C" void kernel_launch(void* const* d_in, const int* in_sizes, int n_in,
                              void* d_out, int out_size)
{
    const int*   idx     = (const int*)  d_in[0];
    const float* tok_emb = (const float*)d_in[1];
    const float* pos_emb = (const float*)d_in[2];
    const float* ln1_g   = (const float*)d_in[3];
    const float* ln1_b   = (const float*)d_in[4];
    const float* wq      = (const float*)d_in[5];
    const float* wk      = (const float*)d_in[6];
    const float* wv      = (const float*)d_in[7];
    const float* proj_w  = (const float*)d_in[8];
    const float* proj_b  = (const float*)d_in[9];
    const float* ln2_g   = (const float*)d_in[10];
    const float* ln2_b   = (const float*)d_in[11];
    const float* w1      = (const float*)d_in[12];
    const float* b1      = (const float*)d_in[13];
    const float* w2      = (const float*)d_in[14];
    const float* b2      = (const float*)d_in[15];
    const float* lnf_g   = (const float*)d_in[16];
    const float* lnf_b   = (const float*)d_in[17];
    const float* lm_w    = (const float*)d_in[18];
    const float* lm_b    = (const float*)d_in[19];
    float* out = (float*)d_out;

    cudaFuncSetAttribute(gemm_mma, cudaFuncAttributeMaxDynamicSharedMemorySize, GEMM_SMEM);

    float *x, *qkv;
    cudaGetSymbolAddress((void**)&x,   g_x);
    cudaGetSymbolAddress((void**)&qkv, g_qkv);
    __nv_bfloat16 *hh,*hl,*ath,*atl,*ffh,*ffl;
    cudaGetSymbolAddress((void**)&hh,  g_hh);  cudaGetSymbolAddress((void**)&hl,  g_hl);
    cudaGetSymbolAddress((void**)&ath, g_ath); cudaGetSymbolAddress((void**)&atl, g_atl);
    cudaGetSymbolAddress((void**)&ffh, g_ffh); cudaGetSymbolAddress((void**)&ffl, g_ffl);
    __nv_bfloat16 *qkvh,*qkvl,*pwh,*pwl,*w1h,*w1l,*w2h,*w2l,*lmh,*lml;
    cudaGetSymbolAddress((void**)&qkvh, g_qkvh); cudaGetSymbolAddress((void**)&qkvl, g_qkvl);
    cudaGetSymbolAddress((void**)&pwh,  g_pwh);  cudaGetSymbolAddress((void**)&pwl,  g_pwl);
    cudaGetSymbolAddress((void**)&w1h,  g_w1h);  cudaGetSymbolAddress((void**)&w1l,  g_w1l);
    cudaGetSymbolAddress((void**)&w2h,  g_w2h);  cudaGetSymbolAddress((void**)&w2l,  g_w2l);
    cudaGetSymbolAddress((void**)&lmh,  g_lmh);  cudaGetSymbolAddress((void**)&lml,  g_lml);

    // ---- prepack all weights in ONE launch ----
    prep_all<<<7136, dim3(32, 8)>>>(wq, wk, wv, proj_w, w1, w2, lm_w,
                                    qkvh, qkvl, pwh, pwl, w1h, w1l,
                                    w2h, w2l, lmh, lml);

    // ---- forward ----
    embed_kernel<<<MROWS, CC>>>(idx, tok_emb, pos_emb, x);

    for (int l = 0; l < LL; l++) {
        ln_kernel<<<MROWS/8, 256>>>(x, ln1_g + l*CC, ln1_b + l*CC, hh, hl);

        launch_gemm(hh, hl, qkvh + (size_t)l*NQKV*CC, qkvl + (size_t)l*NQKV*CC,
                    nullptr, nullptr, qkv, nullptr, nullptr,
                    MROWS, NQKV, NQKV, CC, 0);

        attn_kernel<<<BB*HH, TT>>>(qkv, ath, atl);

        launch_gemm(ath, atl, pwh + (size_t)l*CC*CC, pwl + (size_t)l*CC*CC,
                    proj_b + l*CC, x, x, nullptr, nullptr,
                    MROWS, CC, CC, CC, 0);

        ln_kernel<<<MROWS/8, 256>>>(x, ln2_g + l*CC, ln2_b + l*CC, hh, hl);

        launch_gemm(hh, hl, w1h + (size_t)l*DFF*CC, w1l + (size_t)l*DFF*CC,
                    b1 + l*DFF, nullptr, nullptr, ffh, ffl,
                    MROWS, DFF, DFF, CC, 1);

        launch_gemm(ffh, ffl, w2h + (size_t)l*CC*DFF, w2l + (size_t)l*CC*DFF,
                    b2 + l*CC, x, x, nullptr, nullptr,
                    MROWS, CC, CC, DFF, 0);
    }

    ln_kernel<<<MROWS/8, 256>>>(x, lnf_g, lnf_b, hh, hl);

    launch_gemm(hh, hl, lmh, lml, lm_b, nullptr, out, nullptr, nullptr,
                MROWS, VV, VPAD, CC, 0);
}